// round 4
// baseline (speedup 1.0000x reference)
#include <cuda_runtime.h>
#include <math.h>

#define B_ 256
#define T_ 128
#define D_ 256
#define H_ 512
#define BT_ (B_*T_)
#define G4H_ 2048
#define XHAT_OFF (T_*B_*2)   /* outs [T,B,2] first, then xhats [T,B,D] */
#define LDK 262              /* 262 mod 32 = 6 -> conflict-free u64 row reads */
#define NCTA_LOOP 128

// ---- device scratch (allocation-free rule) ----
__device__ float g_gammaH[(size_t)T_*B_*H_];      // [T,B,H]
__device__ float g_preGates[(size_t)T_*B_*G4H_];  // [T,B,4H]
__device__ float g_part[2][B_][G4H_];             // split-K partials
__device__ float g_hbuf[2][B_][H_];               // double-buffered h
__device__ float g_wT[(D_+H_)*D_];                // wgxT [256,256] then wghT [512,256]
__device__ unsigned g_barC, g_barS;               // grid barrier (self-restoring)

typedef unsigned long long u64;
union F2U { u64 u; float2 f; };

__device__ __forceinline__ u64 ffma2(u64 a, u64 b, u64 c) {
    u64 d; asm("fma.rn.f32x2 %0,%1,%2,%3;" : "=l"(d) : "l"(a), "l"(b), "l"(c)); return d;
}
__device__ __forceinline__ float sigm(float x){ return 1.f/(1.f+expf(-x)); }
__device__ __forceinline__ float ldcg(const float* p){
    float v; asm volatile("ld.global.cg.f32 %0,[%1];" : "=f"(v) : "l"(p)); return v;
}
__device__ __forceinline__ float4 ldcg4(const float* p){
    float4 v; asm volatile("ld.global.cg.v4.f32 {%0,%1,%2,%3},[%4];"
        : "=f"(v.x),"=f"(v.y),"=f"(v.z),"=f"(v.w) : "l"(p)); return v;
}
__device__ __forceinline__ void stcg(float* p, float v){
    asm volatile("st.global.cg.f32 [%0],%1;" :: "l"(p), "f"(v));
}

// ---------------------------------------------------------------------------
// Core 64x128xK256 mainloop, pair-over-K f32x2 FMAs, register double-buffered.
// As:[64][LDK], Bs:[128][LDK], both k-major rows.  tx=tid&15, ty=tid>>4.
// Thread tile: m = ty+16i (i<4), n = tx+16j (j<8).  acc[i][j] pairs over k.
// ---------------------------------------------------------------------------
__device__ __forceinline__ void mm64x128(const float* __restrict__ As,
                                         const float* __restrict__ Bs,
                                         u64 acc[4][8], int tx, int ty)
{
    const float* ar[4];
    const float* br[8];
    #pragma unroll
    for (int i = 0; i < 4; i++) ar[i] = As + (ty + 16*i)*LDK;
    #pragma unroll
    for (int j = 0; j < 8; j++) br[j] = Bs + (tx + 16*j)*LDK;

    u64 a[2][4], w[2][8];
    #pragma unroll
    for (int i = 0; i < 4; i++) a[0][i] = *(const u64*)ar[i];
    #pragma unroll
    for (int j = 0; j < 8; j++) w[0][j] = *(const u64*)br[j];

    #pragma unroll 2
    for (int kp = 0; kp < 128; kp++) {
        const int cur = kp & 1, nxt = cur ^ 1;
        if (kp < 127) {
            #pragma unroll
            for (int i = 0; i < 4; i++) a[nxt][i] = *(const u64*)(ar[i] + 2*(kp+1));
            #pragma unroll
            for (int j = 0; j < 8; j++) w[nxt][j] = *(const u64*)(br[j] + 2*(kp+1));
        }
        #pragma unroll
        for (int i = 0; i < 4; i++)
            #pragma unroll
            for (int j = 0; j < 8; j++)
                acc[i][j] = ffma2(a[cur][i], w[cur][j], acc[i][j]);
    }
}

// direct copy gmem->smem rows (256 floats from col0), stores as u64 pairs
__device__ __forceinline__ void load_tile(float* dst, const float* src,
                                          int rows, int row0, int ld, int col0)
{
    for (int i = threadIdx.x; i < rows*64; i += 256) {
        int r = i >> 6, q = (i & 63) << 2;
        float4 v = *(const float4*)&src[(size_t)(row0+r)*ld + col0 + q];
        u64* d = (u64*)&dst[r*LDK + q];
        F2U lo, hi; lo.f.x = v.x; lo.f.y = v.y; hi.f.x = v.z; hi.f.y = v.w;
        d[0] = lo.u; d[1] = hi.u;
    }
}

// ---------------------------------------------------------------------------
__global__ void __launch_bounds__(H_) k_init(const float* __restrict__ h0)
{
    g_hbuf[0][blockIdx.x][threadIdx.x] = h0[threadIdx.x];
}

// transpose w_gx [K,256] and w_gh [K,512] -> g_wT as [N,K]
__global__ void __launch_bounds__(256) k_tr(const float* __restrict__ wgx,
                                            const float* __restrict__ wgh)
{
    int blk = blockIdx.x, k = threadIdx.x;
    if (blk < 256) g_wT[blk*D_ + k] = wgx[k*D_ + blk];
    else { int n = blk - 256; g_wT[D_*D_ + n*D_ + k] = wgh[k*H_ + n]; }
}

// ---------------------------------------------------------------------------
// G1: gamma_x + imputation -> xhat.  grid (BT/64, 2)
// ---------------------------------------------------------------------------
__global__ void __launch_bounds__(256) k_g1(
    const float* __restrict__ dt,  const float* __restrict__ hgx,
    const float* __restrict__ x,   const float* __restrict__ mask,
    const float* __restrict__ xmean, float* __restrict__ out)
{
    extern __shared__ float sm[];
    float *As = sm, *Bs = sm + 64*LDK;
    int m0 = blockIdx.x*64, n0 = blockIdx.y*128;
    load_tile(As, dt, 64, m0, D_, 0);
    load_tile(Bs, g_wT, 128, n0, D_, 0);
    __syncthreads();
    int tx = threadIdx.x & 15, ty = threadIdx.x >> 4;
    u64 acc[4][8] = {};
    mm64x128(As, Bs, acc, tx, ty);
    #pragma unroll
    for (int i = 0; i < 4; i++) {
        int row = m0 + ty + 16*i;          // row = b*T + t
        int b = row >> 7, t = row & (T_-1);
        #pragma unroll
        for (int j = 0; j < 8; j++) {
            int d = n0 + tx + 16*j;
            F2U v; v.u = acc[i][j];
            float gamma = expf(-fmaxf(v.f.x + v.f.y + hgx[d], 0.f));
            float mv = mask[(size_t)row*D_ + d];
            float xt = x[(size_t)row*D_ + d];
            float xm = xmean[d];
            float imp = (t == 0) ? xm
                      : fmaf(gamma, x[(size_t)(row-1)*D_ + d], (1.f-gamma)*xm);
            out[XHAT_OFF + ((size_t)t*B_ + b)*D_ + d] = xt*mv + (1.f-mv)*imp;
        }
    }
}

// ---------------------------------------------------------------------------
// G2: gamma_h -> g_gammaH.  grid (BT/64, 4)
// ---------------------------------------------------------------------------
__global__ void __launch_bounds__(256) k_g2(
    const float* __restrict__ dt, const float* __restrict__ hgh)
{
    extern __shared__ float sm[];
    float *As = sm, *Bs = sm + 64*LDK;
    int m0 = blockIdx.x*64, n0 = blockIdx.y*128;
    load_tile(As, dt, 64, m0, D_, 0);
    load_tile(Bs, g_wT + D_*D_, 128, n0, D_, 0);
    __syncthreads();
    int tx = threadIdx.x & 15, ty = threadIdx.x >> 4;
    u64 acc[4][8] = {};
    mm64x128(As, Bs, acc, tx, ty);
    #pragma unroll
    for (int i = 0; i < 4; i++) {
        int row = m0 + ty + 16*i;
        int b = row >> 7, t = row & (T_-1);
        #pragma unroll
        for (int j = 0; j < 8; j++) {
            int u = n0 + tx + 16*j;
            F2U v; v.u = acc[i][j];
            g_gammaH[((size_t)t*B_ + b)*H_ + u] = expf(-fmaxf(v.f.x + v.f.y + hgh[u], 0.f));
        }
    }
}

// ---------------------------------------------------------------------------
// G3: pre_gates = xs @ W_ih^T + b_ih + b_hh.  grid (BT/64, 16)
// ---------------------------------------------------------------------------
__global__ void __launch_bounds__(256) k_g3(
    const float* __restrict__ xsrc, const float* __restrict__ Wih,
    const float* __restrict__ bih,  const float* __restrict__ bhh)
{
    extern __shared__ float sm[];
    float *As = sm, *Bs = sm + 64*LDK;
    int m0 = blockIdx.x*64, n0 = blockIdx.y*128;
    load_tile(As, xsrc, 64, m0, D_, 0);
    load_tile(Bs, Wih, 128, n0, D_, 0);
    __syncthreads();
    int tx = threadIdx.x & 15, ty = threadIdx.x >> 4;
    u64 acc[4][8] = {};
    mm64x128(As, Bs, acc, tx, ty);
    #pragma unroll
    for (int i = 0; i < 4; i++) {
        int row = m0 + ty + 16*i;          // row = t*B + b
        #pragma unroll
        for (int j = 0; j < 8; j++) {
            int c = n0 + tx + 16*j;
            F2U v; v.u = acc[i][j];
            g_preGates[(size_t)row*G4H_ + c] = v.f.x + v.f.y + bih[c] + bhh[c];
        }
    }
}

// ---------------------------------------------------------------------------
// grid barrier: acq_rel arrive, release flag, acquire spin (no membar.all)
// 256 passes per launch -> flag returns to 0 (replay-safe)
// ---------------------------------------------------------------------------
__device__ __forceinline__ void gridbar(unsigned &sense)
{
    __syncthreads();
    if (threadIdx.x == 0) {
        unsigned s = sense ^ 1, old;
        asm volatile("atom.acq_rel.gpu.global.add.u32 %0,[%1],1;"
                     : "=r"(old) : "l"(&g_barC));
        if (old == NCTA_LOOP-1) {
            asm volatile("st.relaxed.gpu.global.u32 [%0],%1;" :: "l"(&g_barC), "r"(0u));
            asm volatile("st.release.gpu.global.u32 [%0],%1;" :: "l"(&g_barS), "r"(s));
        } else {
            unsigned v;
            do {
                asm volatile("ld.acquire.gpu.global.u32 %0,[%1];" : "=r"(v) : "l"(&g_barS));
            } while (v != s);
        }
    }
    __syncthreads();
    sense ^= 1;
}

// ---------------------------------------------------------------------------
// Persistent recurrent kernel: 128 CTAs x 256 thr, all 128 steps.
// CTA = (kb, nb, mb): tile b[mb*64,+64) x c[nb*128,+128) x k[kb*256,+256).
// W_hh slice + W1 + tp resident in smem for all steps. c-state in registers.
// ---------------------------------------------------------------------------
__global__ void __launch_bounds__(256) k_loop(
    const float* __restrict__ Whh, const float* __restrict__ c0,
    const float* __restrict__ tp,  const float* __restrict__ wt,
    const float* __restrict__ ht,  const float* __restrict__ W1,
    const float* __restrict__ b1,  const float* __restrict__ W2,
    const float* __restrict__ b2,  float* __restrict__ out)
{
    extern __shared__ float sm[];
    float *Wsm = sm;                      // 128*LDK
    float *ahs = sm + 128*LDK;            // 64*LDK
    float *h1s = sm + 192*LDK;            // 1024
    float *zs  = h1s + 1024;              // 32 (20 used)
    float *W1s = zs + 32;                 // 5120, layout [z][k]
    float *tps = W1s + 5120;              // 256: [2][128]

    const int tid = threadIdx.x, cta = blockIdx.x;
    const int kb = cta & 1, nb = (cta >> 1) & 15, mb = cta >> 5;
    const int b0 = mb*64, c0i = nb*128, k0 = kb*256;
    const int tx = tid & 15, ty = tid >> 4;
    unsigned sense = 0;

    // resident W_hh slice [128 c][256 k]
    load_tile(Wsm, Whh, 128, c0i, H_, k0);
    // resident W1 transposed [z][k] and tp rows for this CTA's 2 batches
    for (int i = tid; i < 5120; i += 256) W1s[i] = W1[(i & 511)*10 + (i >> 9)];
    for (int i = tid; i < 256; i += 256)
        tps[i] = tp[(cta*2 + (i >> 7))*T_ + (i & 127)];

    // cell ownership: 4 items/thread: u = tid + 256*(q&1), b = cta*2 + (q>>1)
    float c_reg[4], wtr[4], htr[4];
    int   ub[4], bb[4];
    #pragma unroll
    for (int q = 0; q < 4; q++) {
        ub[q] = tid + 256*(q & 1);
        bb[q] = cta*2 + (q >> 1);
        c_reg[q] = c0[ub[q]];
        wtr[q] = wt[ub[q]];
        htr[q] = ht[ub[q]];
    }
    __syncthreads();

    for (int t = 0; t < T_; t++) {
        const int p = t & 1;              // GEMM reads hbuf[p], cell writes hbuf[p^1]

        // ---- load h1s for head(t-1) + stage ah(t) = gamma_h ⊙ h ----
        if (t > 0)
            for (int i = tid; i < 1024; i += 256)
                h1s[i] = ldcg(&g_hbuf[p][cta*2 + (i >> 9)][i & 511]);
        for (int i = tid; i < 64*64; i += 256) {
            int r = i >> 6, q = (i & 63) << 2;
            int bg = b0 + r;
            float4 g = *(const float4*)&g_gammaH[((size_t)t*B_ + bg)*H_ + k0 + q];
            float4 h = ldcg4(&g_hbuf[p][bg][k0 + q]);
            g.x *= h.x; g.y *= h.y; g.z *= h.z; g.w *= h.w;
            u64* d = (u64*)&ahs[r*LDK + q];
            F2U lo, hi; lo.f.x = g.x; lo.f.y = g.y; hi.f.x = g.z; hi.f.y = g.w;
            d[0] = lo.u; d[1] = hi.u;
        }
        __syncthreads();

        // ---- output head for step t-1 (reads h1s, W1s in smem) ----
        if (t > 0) {
            int wid = tid >> 5, lane = tid & 31;
            for (int task = wid; task < 20; task += 8) {
                int hb = task / 10, z = task - hb*10;
                float s = 0.f;
                const float* hv = h1s + hb*512;
                const float* wv = W1s + z*512;
                #pragma unroll 4
                for (int k = lane; k < H_; k += 32) s = fmaf(hv[k], wv[k], s);
                #pragma unroll
                for (int off = 16; off; off >>= 1) s += __shfl_xor_sync(0xffffffffu, s, off);
                if (lane == 0) zs[hb*10 + z] = sigm(s + b1[z]);
            }
            __syncthreads();
            if (tid < 2) {
                float z0 = b2[0], z1 = b2[1];
                #pragma unroll
                for (int j = 0; j < 10; j++) {
                    z0 = fmaf(zs[tid*10 + j], W2[j*2 + 0], z0);
                    z1 = fmaf(zs[tid*10 + j], W2[j*2 + 1], z1);
                }
                z0 = sigm(z0); z1 = sigm(z1);
                float m = fmaxf(z0, z1);
                float e0 = expf(z0 - m), e1 = expf(z1 - m);
                float inv = 1.f/(e0 + e1);
                int bg = cta*2 + tid;
                out[((size_t)(t-1)*B_ + bg)*2 + 0] = e0*inv;
                out[((size_t)(t-1)*B_ + bg)*2 + 1] = e1*inv;
            }
        }

        // ---- GEMM slice ----
        u64 acc[4][8] = {};
        mm64x128(ahs, Wsm, acc, tx, ty);
        #pragma unroll
        for (int i = 0; i < 4; i++) {
            int bg = b0 + ty + 16*i;
            #pragma unroll
            for (int j = 0; j < 8; j++) {
                F2U v; v.u = acc[i][j];
                stcg(&g_part[kb][bg][c0i + tx + 16*j], v.f.x + v.f.y);
            }
        }
        gridbar(sense);

        // ---- cell (register c-state) ----
        #pragma unroll
        for (int q = 0; q < 4; q++) {
            int u = ub[q], b = bb[q];
            const float* pre = &g_preGates[((size_t)t*B_ + b)*G4H_];
            float gi = pre[u]        + ldcg(&g_part[0][b][u])        + ldcg(&g_part[1][b][u]);
            float gf = pre[512 + u]  + ldcg(&g_part[0][b][512 + u])  + ldcg(&g_part[1][b][512 + u]);
            float gg = pre[1024 + u] + ldcg(&g_part[0][b][1024 + u]) + ldcg(&g_part[1][b][1024 + u]);
            float go = pre[1536 + u] + ldcg(&g_part[0][b][1536 + u]) + ldcg(&g_part[1][b][1536 + u]);
            float gh = g_gammaH[((size_t)t*B_ + b)*H_ + u];
            float c1 = sigm(gf)*(gh*c_reg[q]) + sigm(gi)*tanhf(gg);
            float h1 = sigm(go)*tanhf(c1);
            float gtv = sigm(tps[(q >> 1)*128 + t]*wtr[q] + htr[q]);
            c_reg[q] = gtv*c1;
            stcg(&g_hbuf[p^1][b][u], gtv*h1);
        }
        gridbar(sense);
    }

    // ---- final head: step 127, h in hbuf[0] ----
    for (int i = tid; i < 1024; i += 256)
        h1s[i] = ldcg(&g_hbuf[0][cta*2 + (i >> 9)][i & 511]);
    __syncthreads();
    {
        int wid = tid >> 5, lane = tid & 31;
        for (int task = wid; task < 20; task += 8) {
            int hb = task / 10, z = task - hb*10;
            float s = 0.f;
            const float* hv = h1s + hb*512;
            const float* wv = W1s + z*512;
            #pragma unroll 4
            for (int k = lane; k < H_; k += 32) s = fmaf(hv[k], wv[k], s);
            #pragma unroll
            for (int off = 16; off; off >>= 1) s += __shfl_xor_sync(0xffffffffu, s, off);
            if (lane == 0) zs[hb*10 + z] = sigm(s + b1[z]);
        }
        __syncthreads();
        if (tid < 2) {
            float z0 = b2[0], z1 = b2[1];
            #pragma unroll
            for (int j = 0; j < 10; j++) {
                z0 = fmaf(zs[tid*10 + j], W2[j*2 + 0], z0);
                z1 = fmaf(zs[tid*10 + j], W2[j*2 + 1], z1);
            }
            z0 = sigm(z0); z1 = sigm(z1);
            float m = fmaxf(z0, z1);
            float e0 = expf(z0 - m), e1 = expf(z1 - m);
            float inv = 1.f/(e0 + e1);
            int bg = cta*2 + tid;
            out[((size_t)127*B_ + bg)*2 + 0] = e0*inv;
            out[((size_t)127*B_ + bg)*2 + 1] = e1*inv;
        }
    }
}

// ---------------------------------------------------------------------------
extern "C" void kernel_launch(void* const* d_in, const int* in_sizes, int n_in,
                              void* d_out, int out_size)
{
    const float* x     = (const float*)d_in[0];
    const float* dt    = (const float*)d_in[1];
    const float* mask  = (const float*)d_in[2];
    const float* tp    = (const float*)d_in[3];
    const float* xmean = (const float*)d_in[4];
    const float* h0    = (const float*)d_in[5];
    const float* c0    = (const float*)d_in[6];
    const float* wgx   = (const float*)d_in[7];
    const float* hgx   = (const float*)d_in[8];
    const float* wgh   = (const float*)d_in[9];
    const float* hgh   = (const float*)d_in[10];
    const float* wt    = (const float*)d_in[11];
    const float* ht    = (const float*)d_in[12];
    const float* Wih   = (const float*)d_in[13];
    const float* Whh   = (const float*)d_in[14];
    const float* bih   = (const float*)d_in[15];
    const float* bhh   = (const float*)d_in[16];
    const float* W1    = (const float*)d_in[17];
    const float* b1    = (const float*)d_in[18];
    const float* W2    = (const float*)d_in[19];
    const float* b2    = (const float*)d_in[20];
    float* out = (float*)d_out;

    const int PRE_SMEM  = (64 + 128) * LDK * 4;                       // 201,216 B
    const int LOOP_SMEM = (192*LDK + 1024 + 32 + 5120 + 256) * 4;     // 226,944 B
    static bool attr_done = false;
    if (!attr_done) {
        cudaFuncSetAttribute(k_g1,  cudaFuncAttributeMaxDynamicSharedMemorySize, PRE_SMEM);
        cudaFuncSetAttribute(k_g2,  cudaFuncAttributeMaxDynamicSharedMemorySize, PRE_SMEM);
        cudaFuncSetAttribute(k_g3,  cudaFuncAttributeMaxDynamicSharedMemorySize, PRE_SMEM);
        cudaFuncSetAttribute(k_loop, cudaFuncAttributeMaxDynamicSharedMemorySize, LOOP_SMEM);
        attr_done = true;
    }

    k_init<<<B_, H_>>>(h0);
    k_tr<<<768, 256>>>(wgx, wgh);
    k_g1<<<dim3(BT_/64, 2),  256, PRE_SMEM>>>(dt, hgx, x, mask, xmean, out);
    k_g2<<<dim3(BT_/64, 4),  256, PRE_SMEM>>>(dt, hgh);
    k_g3<<<dim3(BT_/64, 16), 256, PRE_SMEM>>>(out + XHAT_OFF, Wih, bih, bhh);
    k_loop<<<NCTA_LOOP, 256, LOOP_SMEM>>>(Whh, c0, tp, wt, ht, W1, b1, W2, b2, out);
}

// round 5
// speedup vs baseline: 1.1847x; 1.1847x over previous
#include <cuda_runtime.h>
#include <math.h>

#define B_ 256
#define T_ 128
#define D_ 256
#define H_ 512
#define BT_ (B_*T_)
#define G4H_ 2048
#define XHAT_OFF (T_*B_*2)   /* outs [T,B,2] first, then xhats [T,B,D] */
#define LDK 130              /* Kc=128 rows + 2 pad; 130 mod 32 = 2 -> conflict-free */
#define NCTA_LOOP 256

// ---- device scratch (allocation-free rule) ----
__device__ float g_gammaH[(size_t)T_*B_*H_];      // [T,B,H]
__device__ float g_preGates[(size_t)T_*B_*G4H_];  // [T,B,4H]
__device__ float g_part[4][B_][G4H_];             // split-K partials
__device__ float g_hbuf[2][B_][H_];               // double-buffered h
__device__ float g_wT[(D_+H_)*D_];                // wgxT [256,256] then wghT [512,256]
__device__ float g_W1T[10*H_];                    // W1 transposed [10][512]
__device__ unsigned g_barC, g_barS;               // grid barrier (self-restoring)

typedef unsigned long long u64;
union F2U { u64 u; float2 f; };

__device__ __forceinline__ u64 ffma2(u64 a, u64 b, u64 c) {
    u64 d; asm("fma.rn.f32x2 %0,%1,%2,%3;" : "=l"(d) : "l"(a), "l"(b), "l"(c)); return d;
}
__device__ __forceinline__ float sigm(float x){ return 1.f/(1.f+expf(-x)); }
__device__ __forceinline__ float ldcg(const float* p){
    float v; asm volatile("ld.global.cg.f32 %0,[%1];" : "=f"(v) : "l"(p)); return v;
}
__device__ __forceinline__ float4 ldcg4(const float* p){
    float4 v; asm volatile("ld.global.cg.v4.f32 {%0,%1,%2,%3},[%4];"
        : "=f"(v.x),"=f"(v.y),"=f"(v.z),"=f"(v.w) : "l"(p)); return v;
}
__device__ __forceinline__ void stcg(float* p, float v){
    asm volatile("st.global.cg.f32 [%0],%1;" :: "l"(p), "f"(v));
}

// ---------------------------------------------------------------------------
// 64x128 x Kc=128 mainloop, pair-over-K f32x2. As:[64][LDK], Bs:[128][LDK].
// tx=tid&15 -> n = tx+16j (j<8); ty=tid>>4 -> m = ty+16i (i<4). acc[i][j].
// ---------------------------------------------------------------------------
__device__ __forceinline__ void mm64(const float* __restrict__ As,
                                     const float* __restrict__ Bs,
                                     u64 acc[4][8], int tx, int ty)
{
    #pragma unroll 2
    for (int kp = 0; kp < 64; kp++) {
        u64 a[4], w[8];
        #pragma unroll
        for (int i = 0; i < 4; i++) a[i] = *(const u64*)&As[(ty+16*i)*LDK + 2*kp];
        #pragma unroll
        for (int j = 0; j < 8; j++) w[j] = *(const u64*)&Bs[(tx+16*j)*LDK + 2*kp];
        #pragma unroll
        for (int i = 0; i < 4; i++)
            #pragma unroll
            for (int j = 0; j < 8; j++) acc[i][j] = ffma2(a[i], w[j], acc[i][j]);
    }
}

// copy gmem->smem: rows x 128 floats starting at col0 (u64 stores: 8B aligned)
__device__ __forceinline__ void load_tile(float* dst, const float* src,
                                          int rows, int row0, int ld, int col0)
{
    for (int i = threadIdx.x; i < rows*32; i += 256) {
        int r = i >> 5, q = (i & 31) << 2;
        float4 v = *(const float4*)&src[(size_t)(row0+r)*ld + col0 + q];
        u64* d = (u64*)&dst[r*LDK + q];
        F2U lo, hi; lo.f.x = v.x; lo.f.y = v.y; hi.f.x = v.z; hi.f.y = v.w;
        d[0] = lo.u; d[1] = hi.u;
    }
}

// ---------------------------------------------------------------------------
__global__ void __launch_bounds__(H_) k_init(const float* __restrict__ h0)
{
    g_hbuf[0][blockIdx.x][threadIdx.x] = h0[threadIdx.x];
}

// transposes: wgx[256,256]->g_wT[0:256), wgh[256,512]->g_wT[256:768), W1[512,10]->g_W1T
__global__ void __launch_bounds__(256) k_tr(const float* __restrict__ wgx,
                                            const float* __restrict__ wgh,
                                            const float* __restrict__ W1)
{
    int blk = blockIdx.x, k = threadIdx.x;
    if (blk < 256) g_wT[blk*D_ + k] = wgx[k*D_ + blk];
    else if (blk < 768) { int n = blk - 256; g_wT[D_*D_ + n*D_ + k] = wgh[k*H_ + n]; }
    else {
        int z = blk - 768;
        g_W1T[z*H_ + k]       = W1[k*10 + z];
        g_W1T[z*H_ + k + 256] = W1[(k+256)*10 + z];
    }
}

// ---------------------------------------------------------------------------
// G12: gamma_x (+imputation->xhat) and gamma_h fused.  grid (BT/64, 6).
//   by<2: gamma_x columns (d = by*128+...), else gamma_h (u = by*128-256+...)
// ---------------------------------------------------------------------------
__global__ void __launch_bounds__(256,2) k_g12(
    const float* __restrict__ dt,  const float* __restrict__ hgx,
    const float* __restrict__ hgh, const float* __restrict__ x,
    const float* __restrict__ mask, const float* __restrict__ xmean,
    float* __restrict__ out)
{
    extern __shared__ float sm[];
    float *As = sm, *Bs = sm + 64*LDK;
    int m0 = blockIdx.x*64, n0 = blockIdx.y*128;
    int tx = threadIdx.x & 15, ty = threadIdx.x >> 4;
    u64 acc[4][8] = {};
    #pragma unroll
    for (int c = 0; c < 2; c++) {
        if (c) __syncthreads();            // WAR: previous compute done
        load_tile(As, dt,   64,  m0, D_, c*128);
        load_tile(Bs, g_wT, 128, n0, D_, c*128);
        __syncthreads();
        mm64(As, Bs, acc, tx, ty);
    }
    if (blockIdx.y < 2) {
        #pragma unroll
        for (int i = 0; i < 4; i++) {
            int row = m0 + ty + 16*i;      // row = b*T + t
            int b = row >> 7, t = row & (T_-1);
            #pragma unroll
            for (int j = 0; j < 8; j++) {
                int d = n0 + tx + 16*j;
                F2U v; v.u = acc[i][j];
                float gamma = expf(-fmaxf(v.f.x + v.f.y + hgx[d], 0.f));
                float mv = mask[(size_t)row*D_ + d];
                float xt = x[(size_t)row*D_ + d];
                float xm = xmean[d];
                float imp = (t == 0) ? xm
                          : fmaf(gamma, x[(size_t)(row-1)*D_ + d], (1.f-gamma)*xm);
                out[XHAT_OFF + ((size_t)t*B_ + b)*D_ + d] = xt*mv + (1.f-mv)*imp;
            }
        }
    } else {
        #pragma unroll
        for (int i = 0; i < 4; i++) {
            int row = m0 + ty + 16*i;
            int b = row >> 7, t = row & (T_-1);
            #pragma unroll
            for (int j = 0; j < 8; j++) {
                int u = n0 - 256 + tx + 16*j;
                F2U v; v.u = acc[i][j];
                g_gammaH[((size_t)t*B_ + b)*H_ + u] = expf(-fmaxf(v.f.x + v.f.y + hgh[u], 0.f));
            }
        }
    }
}

// ---------------------------------------------------------------------------
// G3: pre_gates = xs @ W_ih^T + b_ih + b_hh.  grid (BT/64, 16)
// ---------------------------------------------------------------------------
__global__ void __launch_bounds__(256,2) k_g3(
    const float* __restrict__ xsrc, const float* __restrict__ Wih,
    const float* __restrict__ bih,  const float* __restrict__ bhh)
{
    extern __shared__ float sm[];
    float *As = sm, *Bs = sm + 64*LDK;
    int m0 = blockIdx.x*64, n0 = blockIdx.y*128;
    int tx = threadIdx.x & 15, ty = threadIdx.x >> 4;
    u64 acc[4][8] = {};
    #pragma unroll
    for (int c = 0; c < 2; c++) {
        if (c) __syncthreads();
        load_tile(As, xsrc, 64,  m0, D_, c*128);
        load_tile(Bs, Wih,  128, n0, D_, c*128);
        __syncthreads();
        mm64(As, Bs, acc, tx, ty);
    }
    #pragma unroll
    for (int i = 0; i < 4; i++) {
        int row = m0 + ty + 16*i;          // row = t*B + b
        #pragma unroll
        for (int j = 0; j < 8; j++) {
            int c = n0 + tx + 16*j;
            F2U v; v.u = acc[i][j];
            g_preGates[(size_t)row*G4H_ + c] = v.f.x + v.f.y + bih[c] + bhh[c];
        }
    }
}

// ---------------------------------------------------------------------------
// grid barrier: acq_rel arrive, release flag, acquire spin.
// 256 passes/launch -> even -> replay-safe.
// ---------------------------------------------------------------------------
__device__ __forceinline__ void gridbar(unsigned &sense)
{
    __syncthreads();
    if (threadIdx.x == 0) {
        unsigned s = sense ^ 1, old;
        asm volatile("atom.acq_rel.gpu.global.add.u32 %0,[%1],1;"
                     : "=r"(old) : "l"(&g_barC));
        if (old == NCTA_LOOP-1) {
            asm volatile("st.relaxed.gpu.global.u32 [%0],%1;" :: "l"(&g_barC), "r"(0u));
            asm volatile("st.release.gpu.global.u32 [%0],%1;" :: "l"(&g_barS), "r"(s));
        } else {
            unsigned v;
            do {
                asm volatile("ld.acquire.gpu.global.u32 %0,[%1];" : "=r"(v) : "l"(&g_barS));
            } while (v != s);
        }
    }
    __syncthreads();
    sense ^= 1;
}

// ---------------------------------------------------------------------------
// Persistent recurrent kernel: 256 CTAs x 256 thr, all 128 steps.
// CTA = (kb,nb,mb): tile b[mb*64,+64) x c[nb*128,+128) x k[kb*128,+128).
// W_hh slice resident in smem. c-state in registers (b = cta, 2 items/thread).
// ---------------------------------------------------------------------------
__global__ void __launch_bounds__(256,2) k_loop(
    const float* __restrict__ Whh, const float* __restrict__ c0,
    const float* __restrict__ tp,  const float* __restrict__ wt,
    const float* __restrict__ ht,  const float* __restrict__ b1,
    const float* __restrict__ W2,  const float* __restrict__ b2,
    float* __restrict__ out)
{
    extern __shared__ float sm[];
    float *Wsm = sm;                      // 128*LDK
    float *ahs = sm + 128*LDK;            // 64*LDK
    float *h1s = sm + 192*LDK;            // 512
    float *zs  = h1s + 512;               // 16 (10 used)
    float *tps = zs + 16;                 // 128

    const int tid = threadIdx.x, cta = blockIdx.x;
    const int kb = cta & 3, nb = (cta >> 2) & 15, mb = cta >> 6;
    const int b0 = mb*64, c0i = nb*128, k0 = kb*128;
    const int tx = tid & 15, ty = tid >> 4;
    unsigned sense = 0;

    // resident W_hh slice [128 c][128 k]
    load_tile(Wsm, Whh, 128, c0i, H_, k0);
    // tp series for this CTA's batch (b = cta)
    for (int i = tid; i < 128; i += 256) tps[i] = tp[cta*T_ + i];

    // cell ownership: b = cta, u = tid + 256*q (q<2)
    float c_reg[2], wtr[2], htr[2];
    #pragma unroll
    for (int q = 0; q < 2; q++) {
        c_reg[q] = c0[tid + 256*q];
        wtr[q]   = wt[tid + 256*q];
        htr[q]   = ht[tid + 256*q];
    }
    __syncthreads();

    for (int t = 0; t < T_; t++) {
        const int p = t & 1;              // GEMM reads hbuf[p], cell writes hbuf[p^1]

        // ---- stage h1s (for head t-1, b=cta) + ah = gamma_h ⊙ h ----
        if (t > 0)
            for (int i = tid; i < 512; i += 256)
                h1s[i] = ldcg(&g_hbuf[p][cta][i]);
        for (int i = tid; i < 64*32; i += 256) {
            int r = i >> 5, q = (i & 31) << 2;
            int bg = b0 + r;
            float4 g = *(const float4*)&g_gammaH[((size_t)t*B_ + bg)*H_ + k0 + q];
            float4 h = ldcg4(&g_hbuf[p][bg][k0 + q]);
            g.x *= h.x; g.y *= h.y; g.z *= h.z; g.w *= h.w;
            u64* d = (u64*)&ahs[r*LDK + q];
            F2U lo, hi; lo.f.x = g.x; lo.f.y = g.y; hi.f.x = g.z; hi.f.y = g.w;
            d[0] = lo.u; d[1] = hi.u;
        }
        __syncthreads();

        // ---- output head for step t-1 (batch cta) ----
        if (t > 0) {
            int wid = tid >> 5, lane = tid & 31;
            for (int z = wid; z < 10; z += 8) {
                float s = 0.f;
                const float* wv = g_W1T + z*H_;
                #pragma unroll 4
                for (int k = lane; k < H_; k += 32) s = fmaf(h1s[k], __ldg(&wv[k]), s);
                #pragma unroll
                for (int off = 16; off; off >>= 1) s += __shfl_xor_sync(0xffffffffu, s, off);
                if (lane == 0) zs[z] = sigm(s + b1[z]);
            }
            __syncthreads();
            if (tid == 0) {
                float z0 = b2[0], z1 = b2[1];
                #pragma unroll
                for (int j = 0; j < 10; j++) {
                    z0 = fmaf(zs[j], W2[j*2 + 0], z0);
                    z1 = fmaf(zs[j], W2[j*2 + 1], z1);
                }
                z0 = sigm(z0); z1 = sigm(z1);
                float m = fmaxf(z0, z1);
                float e0 = expf(z0 - m), e1 = expf(z1 - m);
                float inv = 1.f/(e0 + e1);
                out[((size_t)(t-1)*B_ + cta)*2 + 0] = e0*inv;
                out[((size_t)(t-1)*B_ + cta)*2 + 1] = e1*inv;
            }
        }

        // ---- GEMM slice: 64x128x128 ----
        u64 acc[4][8] = {};
        mm64(ahs, Wsm, acc, tx, ty);
        #pragma unroll
        for (int i = 0; i < 4; i++) {
            int bg = b0 + ty + 16*i;
            #pragma unroll
            for (int j = 0; j < 8; j++) {
                F2U v; v.u = acc[i][j];
                stcg(&g_part[kb][bg][c0i + tx + 16*j], v.f.x + v.f.y);
            }
        }
        gridbar(sense);

        // ---- cell (register c-state), b = cta ----
        #pragma unroll
        for (int q = 0; q < 2; q++) {
            int u = tid + 256*q;
            const float* pre = &g_preGates[((size_t)t*B_ + cta)*G4H_];
            float gi = pre[u]        + ldcg(&g_part[0][cta][u])        + ldcg(&g_part[1][cta][u])
                                     + ldcg(&g_part[2][cta][u])        + ldcg(&g_part[3][cta][u]);
            float gf = pre[512 + u]  + ldcg(&g_part[0][cta][512 + u])  + ldcg(&g_part[1][cta][512 + u])
                                     + ldcg(&g_part[2][cta][512 + u])  + ldcg(&g_part[3][cta][512 + u]);
            float gg = pre[1024 + u] + ldcg(&g_part[0][cta][1024 + u]) + ldcg(&g_part[1][cta][1024 + u])
                                     + ldcg(&g_part[2][cta][1024 + u]) + ldcg(&g_part[3][cta][1024 + u]);
            float go = pre[1536 + u] + ldcg(&g_part[0][cta][1536 + u]) + ldcg(&g_part[1][cta][1536 + u])
                                     + ldcg(&g_part[2][cta][1536 + u]) + ldcg(&g_part[3][cta][1536 + u]);
            float gh = g_gammaH[((size_t)t*B_ + cta)*H_ + u];
            float c1 = sigm(gf)*(gh*c_reg[q]) + sigm(gi)*tanhf(gg);
            float h1 = sigm(go)*tanhf(c1);
            float gtv = sigm(tps[t]*wtr[q] + htr[q]);
            c_reg[q] = gtv*c1;
            stcg(&g_hbuf[p^1][cta][u], gtv*h1);
        }
        gridbar(sense);
    }

    // ---- final head: step 127, h in hbuf[0], batch cta ----
    for (int i = tid; i < 512; i += 256)
        h1s[i] = ldcg(&g_hbuf[0][cta][i]);
    __syncthreads();
    {
        int wid = tid >> 5, lane = tid & 31;
        for (int z = wid; z < 10; z += 8) {
            float s = 0.f;
            const float* wv = g_W1T + z*H_;
            #pragma unroll 4
            for (int k = lane; k < H_; k += 32) s = fmaf(h1s[k], __ldg(&wv[k]), s);
            #pragma unroll
            for (int off = 16; off; off >>= 1) s += __shfl_xor_sync(0xffffffffu, s, off);
            if (lane == 0) zs[z] = sigm(s + b1[z]);
        }
        __syncthreads();
        if (tid == 0) {
            float z0 = b2[0], z1 = b2[1];
            #pragma unroll
            for (int j = 0; j < 10; j++) {
                z0 = fmaf(zs[j], W2[j*2 + 0], z0);
                z1 = fmaf(zs[j], W2[j*2 + 1], z1);
            }
            z0 = sigm(z0); z1 = sigm(z1);
            float m = fmaxf(z0, z1);
            float e0 = expf(z0 - m), e1 = expf(z1 - m);
            float inv = 1.f/(e0 + e1);
            out[((size_t)127*B_ + cta)*2 + 0] = e0*inv;
            out[((size_t)127*B_ + cta)*2 + 1] = e1*inv;
        }
    }
}

// ---------------------------------------------------------------------------
extern "C" void kernel_launch(void* const* d_in, const int* in_sizes, int n_in,
                              void* d_out, int out_size)
{
    const float* x     = (const float*)d_in[0];
    const float* dt    = (const float*)d_in[1];
    const float* mask  = (const float*)d_in[2];
    const float* tp    = (const float*)d_in[3];
    const float* xmean = (const float*)d_in[4];
    const float* h0    = (const float*)d_in[5];
    const float* c0    = (const float*)d_in[6];
    const float* wgx   = (const float*)d_in[7];
    const float* hgx   = (const float*)d_in[8];
    const float* wgh   = (const float*)d_in[9];
    const float* hgh   = (const float*)d_in[10];
    const float* wt    = (const float*)d_in[11];
    const float* ht    = (const float*)d_in[12];
    const float* Wih   = (const float*)d_in[13];
    const float* Whh   = (const float*)d_in[14];
    const float* bih   = (const float*)d_in[15];
    const float* bhh   = (const float*)d_in[16];
    const float* W1    = (const float*)d_in[17];
    const float* b1    = (const float*)d_in[18];
    const float* W2    = (const float*)d_in[19];
    const float* b2    = (const float*)d_in[20];
    float* out = (float*)d_out;

    const int PRE_SMEM  = (64 + 128) * LDK * 4;                     //  99,840 B
    const int LOOP_SMEM = (192*LDK + 512 + 16 + 128) * 4;           // 102,464 B
    static bool attr_done = false;
    if (!attr_done) {
        cudaFuncSetAttribute(k_g12, cudaFuncAttributeMaxDynamicSharedMemorySize, PRE_SMEM);
        cudaFuncSetAttribute(k_g3,  cudaFuncAttributeMaxDynamicSharedMemorySize, PRE_SMEM);
        cudaFuncSetAttribute(k_loop, cudaFuncAttributeMaxDynamicSharedMemorySize, LOOP_SMEM);
        attr_done = true;
    }

    k_init<<<B_, H_>>>(h0);
    k_tr<<<778, 256>>>(wgx, wgh, W1);
    k_g12<<<dim3(BT_/64, 6),  256, PRE_SMEM>>>(dt, hgx, hgh, x, mask, xmean, out);
    k_g3<<<dim3(BT_/64, 16), 256, PRE_SMEM>>>(out + XHAT_OFF, Wih, bih, bhh);
    k_loop<<<NCTA_LOOP, 256, LOOP_SMEM>>>(Whh, c0, tp, wt, ht, b1, W2, b2, out);
}

// round 6
// speedup vs baseline: 1.2529x; 1.0575x over previous
#include <cuda_runtime.h>
#include <math.h>

#define B_ 256
#define T_ 128
#define D_ 256
#define H_ 512
#define BT_ (B_*T_)
#define G4H_ 2048
#define XHAT_OFF (T_*B_*2)   /* outs [T,B,2] first, then xhats [T,B,D] */
#define LDK 132              /* Kc=128 + 4 pad; rows 16B-aligned, phase-conflict-free */
#define NCTA_HALF 128        /* loop runs as 2 independent halves of 128 CTAs */

// ---- device scratch (allocation-free rule) ----
__device__ float g_gammaH[(size_t)T_*B_*H_];      // [T,B,H]
__device__ float g_preGates[(size_t)T_*B_*G4H_];  // [T,B,4H]
__device__ float g_part[4][B_][G4H_];             // split-K partials
__device__ float g_hbuf[2][B_][H_];               // double-buffered h
__device__ float g_wT[(D_+H_)*D_];                // wgxT [256,256] then wghT [512,256]
__device__ float g_W1T[10*H_];                    // W1 transposed [10][512]
__device__ unsigned g_barC[2][32];                // per-half barrier counter (128B apart)
__device__ unsigned g_barS[2][32];                // per-half barrier flag

typedef unsigned long long u64;
union F2U { u64 u; float2 f; };

__device__ __forceinline__ u64 ffma2(u64 a, u64 b, u64 c) {
    u64 d; asm("fma.rn.f32x2 %0,%1,%2,%3;" : "=l"(d) : "l"(a), "l"(b), "l"(c)); return d;
}
__device__ __forceinline__ float sigm(float x){ return 1.f/(1.f+expf(-x)); }
__device__ __forceinline__ float ldcg(const float* p){
    float v; asm volatile("ld.global.cg.f32 %0,[%1];" : "=f"(v) : "l"(p)); return v;
}
__device__ __forceinline__ float4 ldcg4(const float* p){
    float4 v; asm volatile("ld.global.cg.v4.f32 {%0,%1,%2,%3},[%4];"
        : "=f"(v.x),"=f"(v.y),"=f"(v.z),"=f"(v.w) : "l"(p)); return v;
}
__device__ __forceinline__ void stcg(float* p, float v){
    asm volatile("st.global.cg.f32 [%0],%1;" :: "l"(p), "f"(v));
}

// ---------------------------------------------------------------------------
// 64x128 x Kc=128 mainloop, LDS.128 (4 k per load), pair-over-K f32x2 FMAs.
// As:[64][LDK], Bs:[128][LDK].  tx=tid&15 -> n=tx+16j (j<8); ty=tid>>4 ->
// m=ty+16i (i<4).  Per iter: 12 LDS.128 + 64 FFMA2  -> ~80% fma issue ceiling.
// ---------------------------------------------------------------------------
__device__ __forceinline__ void mm64(const float* __restrict__ As,
                                     const float* __restrict__ Bs,
                                     u64 acc[4][8], int tx, int ty)
{
    #pragma unroll 1
    for (int k4 = 0; k4 < 32; k4++) {
        float4 a4[4], w4[8];
        #pragma unroll
        for (int i = 0; i < 4; i++) a4[i] = *(const float4*)&As[(ty+16*i)*LDK + 4*k4];
        #pragma unroll
        for (int j = 0; j < 8; j++) w4[j] = *(const float4*)&Bs[(tx+16*j)*LDK + 4*k4];
        #pragma unroll
        for (int i = 0; i < 4; i++) {
            u64 alo = ((const u64*)&a4[i])[0], ahi = ((const u64*)&a4[i])[1];
            #pragma unroll
            for (int j = 0; j < 8; j++) {
                acc[i][j] = ffma2(alo, ((const u64*)&w4[j])[0], acc[i][j]);
                acc[i][j] = ffma2(ahi, ((const u64*)&w4[j])[1], acc[i][j]);
            }
        }
    }
}

// copy gmem->smem: rows x 128 floats starting at col0 (16B-aligned stores)
__device__ __forceinline__ void load_tile(float* dst, const float* src,
                                          int rows, int row0, int ld, int col0)
{
    for (int i = threadIdx.x; i < rows*32; i += 256) {
        int r = i >> 5, q = (i & 31) << 2;
        *(float4*)&dst[r*LDK + q] = *(const float4*)&src[(size_t)(row0+r)*ld + col0 + q];
    }
}

// ---------------------------------------------------------------------------
__global__ void __launch_bounds__(H_) k_init(const float* __restrict__ h0)
{
    g_hbuf[0][blockIdx.x][threadIdx.x] = h0[threadIdx.x];
}

// transposes: wgx[256,256]->g_wT[0:256), wgh[256,512]->g_wT[256:768), W1->g_W1T
__global__ void __launch_bounds__(256) k_tr(const float* __restrict__ wgx,
                                            const float* __restrict__ wgh,
                                            const float* __restrict__ W1)
{
    int blk = blockIdx.x, k = threadIdx.x;
    if (blk < 256) g_wT[blk*D_ + k] = wgx[k*D_ + blk];
    else if (blk < 768) { int n = blk - 256; g_wT[D_*D_ + n*D_ + k] = wgh[k*H_ + n]; }
    else {
        int z = blk - 768;
        g_W1T[z*H_ + k]       = W1[k*10 + z];
        g_W1T[z*H_ + k + 256] = W1[(k+256)*10 + z];
    }
}

// ---------------------------------------------------------------------------
// G12: gamma_x (+imputation->xhat) and gamma_h fused.  grid (BT/64, 6).
// ---------------------------------------------------------------------------
__global__ void __launch_bounds__(256,2) k_g12(
    const float* __restrict__ dt,  const float* __restrict__ hgx,
    const float* __restrict__ hgh, const float* __restrict__ x,
    const float* __restrict__ mask, const float* __restrict__ xmean,
    float* __restrict__ out)
{
    extern __shared__ float sm[];
    float *As = sm, *Bs = sm + 64*LDK;
    int m0 = blockIdx.x*64, n0 = blockIdx.y*128;
    int tx = threadIdx.x & 15, ty = threadIdx.x >> 4;
    u64 acc[4][8] = {};
    #pragma unroll
    for (int c = 0; c < 2; c++) {
        if (c) __syncthreads();
        load_tile(As, dt,   64,  m0, D_, c*128);
        load_tile(Bs, g_wT, 128, n0, D_, c*128);
        __syncthreads();
        mm64(As, Bs, acc, tx, ty);
    }
    if (blockIdx.y < 2) {
        #pragma unroll
        for (int i = 0; i < 4; i++) {
            int row = m0 + ty + 16*i;      // row = b*T + t
            int b = row >> 7, t = row & (T_-1);
            #pragma unroll
            for (int j = 0; j < 8; j++) {
                int d = n0 + tx + 16*j;
                F2U v; v.u = acc[i][j];
                float gamma = expf(-fmaxf(v.f.x + v.f.y + hgx[d], 0.f));
                float mv = mask[(size_t)row*D_ + d];
                float xt = x[(size_t)row*D_ + d];
                float xm = xmean[d];
                float imp = (t == 0) ? xm
                          : fmaf(gamma, x[(size_t)(row-1)*D_ + d], (1.f-gamma)*xm);
                out[XHAT_OFF + ((size_t)t*B_ + b)*D_ + d] = xt*mv + (1.f-mv)*imp;
            }
        }
    } else {
        #pragma unroll
        for (int i = 0; i < 4; i++) {
            int row = m0 + ty + 16*i;
            int b = row >> 7, t = row & (T_-1);
            #pragma unroll
            for (int j = 0; j < 8; j++) {
                int u = n0 - 256 + tx + 16*j;
                F2U v; v.u = acc[i][j];
                g_gammaH[((size_t)t*B_ + b)*H_ + u] = expf(-fmaxf(v.f.x + v.f.y + hgh[u], 0.f));
            }
        }
    }
}

// ---------------------------------------------------------------------------
// G3: pre_gates = xs @ W_ih^T + b_ih + b_hh.  grid (BT/64, 16)
// ---------------------------------------------------------------------------
__global__ void __launch_bounds__(256,2) k_g3(
    const float* __restrict__ xsrc, const float* __restrict__ Wih,
    const float* __restrict__ bih,  const float* __restrict__ bhh)
{
    extern __shared__ float sm[];
    float *As = sm, *Bs = sm + 64*LDK;
    int m0 = blockIdx.x*64, n0 = blockIdx.y*128;
    int tx = threadIdx.x & 15, ty = threadIdx.x >> 4;
    u64 acc[4][8] = {};
    #pragma unroll
    for (int c = 0; c < 2; c++) {
        if (c) __syncthreads();
        load_tile(As, xsrc, 64,  m0, D_, c*128);
        load_tile(Bs, Wih,  128, n0, D_, c*128);
        __syncthreads();
        mm64(As, Bs, acc, tx, ty);
    }
    #pragma unroll
    for (int i = 0; i < 4; i++) {
        int row = m0 + ty + 16*i;          // row = t*B + b
        #pragma unroll
        for (int j = 0; j < 8; j++) {
            int c = n0 + tx + 16*j;
            F2U v; v.u = acc[i][j];
            g_preGates[(size_t)row*G4H_ + c] = v.f.x + v.f.y + bih[c] + bhh[c];
        }
    }
}

// ---------------------------------------------------------------------------
// per-half grid barrier (128 CTAs): acq_rel arrive, release flag, acquire spin.
// 256 passes/launch per half -> flag returns to initial value (replay-safe).
// ---------------------------------------------------------------------------
__device__ __forceinline__ void gridbar(int half, unsigned &sense)
{
    __syncthreads();
    if (threadIdx.x == 0) {
        unsigned s = sense ^ 1, old;
        asm volatile("atom.acq_rel.gpu.global.add.u32 %0,[%1],1;"
                     : "=r"(old) : "l"(&g_barC[half][0]));
        if (old == NCTA_HALF-1) {
            asm volatile("st.relaxed.gpu.global.u32 [%0],%1;" :: "l"(&g_barC[half][0]), "r"(0u));
            asm volatile("st.release.gpu.global.u32 [%0],%1;" :: "l"(&g_barS[half][0]), "r"(s));
        } else {
            unsigned v;
            do {
                asm volatile("ld.acquire.gpu.global.u32 %0,[%1];" : "=r"(v) : "l"(&g_barS[half][0]));
            } while (v != s);
        }
    }
    __syncthreads();
    sense ^= 1;
}

// ---------------------------------------------------------------------------
// Persistent recurrent kernel: 2 independent halves x 128 CTAs, 128 steps.
// Half = batches [half*128, +128).  local CTA = (kb,nb,mb):
//   tile b[half*128+mb*64,+64) x c[nb*128,+128) x k[kb*128,+128).
// The halves never sync with each other -> anti-phase overlap on shared SMs.
// ---------------------------------------------------------------------------
__global__ void __launch_bounds__(256,2) k_loop(
    const float* __restrict__ Whh, const float* __restrict__ c0,
    const float* __restrict__ tp,  const float* __restrict__ wt,
    const float* __restrict__ ht,  const float* __restrict__ b1,
    const float* __restrict__ W2,  const float* __restrict__ b2,
    float* __restrict__ out)
{
    extern __shared__ float sm[];
    float *Wsm = sm;                      // 128*LDK
    float *ahs = sm + 128*LDK;            // 64*LDK
    float *h1s = sm + 192*LDK;            // 512
    float *zs  = h1s + 512;               // 16 (10 used)
    float *tps = zs + 16;                 // 128

    const int tid = threadIdx.x;
    const int half  = (blockIdx.x < 128) ? 0 : 1;
    const int local = blockIdx.x - half*128;
    const int kb = local & 3, nb = (local >> 2) & 15, mb = local >> 6;
    const int b0 = half*128 + mb*64, c0i = nb*128, k0 = kb*128;
    const int bc = half*128 + local;      // this CTA's cell batch
    const int tx = tid & 15, ty = tid >> 4;
    unsigned sense = 0;

    // resident W_hh slice [128 c][128 k]
    load_tile(Wsm, Whh, 128, c0i, H_, k0);
    for (int i = tid; i < 128; i += 256) tps[i] = tp[bc*T_ + i];

    // cell ownership: b = bc, u = tid + 256*q (q<2)
    float c_reg[2], wtr[2], htr[2];
    #pragma unroll
    for (int q = 0; q < 2; q++) {
        c_reg[q] = c0[tid + 256*q];
        wtr[q]   = wt[tid + 256*q];
        htr[q]   = ht[tid + 256*q];
    }
    __syncthreads();

    for (int t = 0; t < T_; t++) {
        const int p = t & 1;              // GEMM reads hbuf[p], cell writes hbuf[p^1]

        // ---- stage h1s (head t-1, batch bc) + ah = gamma_h ⊙ h ----
        if (t > 0)
            for (int i = tid; i < 512; i += 256)
                h1s[i] = ldcg(&g_hbuf[p][bc][i]);
        for (int i = tid; i < 64*32; i += 256) {
            int r = i >> 5, q = (i & 31) << 2;
            int bg = b0 + r;
            float4 g = *(const float4*)&g_gammaH[((size_t)t*B_ + bg)*H_ + k0 + q];
            float4 h = ldcg4(&g_hbuf[p][bg][k0 + q]);
            g.x *= h.x; g.y *= h.y; g.z *= h.z; g.w *= h.w;
            *(float4*)&ahs[r*LDK + q] = g;
        }
        __syncthreads();

        // ---- output head for step t-1 (batch bc) ----
        if (t > 0) {
            int wid = tid >> 5, lane = tid & 31;
            for (int z = wid; z < 10; z += 8) {
                float s = 0.f;
                const float* wv = g_W1T + z*H_;
                #pragma unroll 4
                for (int k = lane; k < H_; k += 32) s = fmaf(h1s[k], __ldg(&wv[k]), s);
                #pragma unroll
                for (int off = 16; off; off >>= 1) s += __shfl_xor_sync(0xffffffffu, s, off);
                if (lane == 0) zs[z] = sigm(s + b1[z]);
            }
            __syncthreads();
            if (tid == 0) {
                float z0 = b2[0], z1 = b2[1];
                #pragma unroll
                for (int j = 0; j < 10; j++) {
                    z0 = fmaf(zs[j], W2[j*2 + 0], z0);
                    z1 = fmaf(zs[j], W2[j*2 + 1], z1);
                }
                z0 = sigm(z0); z1 = sigm(z1);
                float m = fmaxf(z0, z1);
                float e0 = expf(z0 - m), e1 = expf(z1 - m);
                float inv = 1.f/(e0 + e1);
                out[((size_t)(t-1)*B_ + bc)*2 + 0] = e0*inv;
                out[((size_t)(t-1)*B_ + bc)*2 + 1] = e1*inv;
            }
        }

        // ---- GEMM slice: 64x128x128 ----
        u64 acc[4][8] = {};
        mm64(ahs, Wsm, acc, tx, ty);
        #pragma unroll
        for (int i = 0; i < 4; i++) {
            int bg = b0 + ty + 16*i;
            #pragma unroll
            for (int j = 0; j < 8; j++) {
                F2U v; v.u = acc[i][j];
                stcg(&g_part[kb][bg][c0i + tx + 16*j], v.f.x + v.f.y);
            }
        }
        gridbar(half, sense);

        // ---- cell (register c-state), batch bc ----
        #pragma unroll
        for (int q = 0; q < 2; q++) {
            int u = tid + 256*q;
            const float* pre = &g_preGates[((size_t)t*B_ + bc)*G4H_];
            float gi = pre[u]        + ldcg(&g_part[0][bc][u])        + ldcg(&g_part[1][bc][u])
                                     + ldcg(&g_part[2][bc][u])        + ldcg(&g_part[3][bc][u]);
            float gf = pre[512 + u]  + ldcg(&g_part[0][bc][512 + u])  + ldcg(&g_part[1][bc][512 + u])
                                     + ldcg(&g_part[2][bc][512 + u])  + ldcg(&g_part[3][bc][512 + u]);
            float gg = pre[1024 + u] + ldcg(&g_part[0][bc][1024 + u]) + ldcg(&g_part[1][bc][1024 + u])
                                     + ldcg(&g_part[2][bc][1024 + u]) + ldcg(&g_part[3][bc][1024 + u]);
            float go = pre[1536 + u] + ldcg(&g_part[0][bc][1536 + u]) + ldcg(&g_part[1][bc][1536 + u])
                                     + ldcg(&g_part[2][bc][1536 + u]) + ldcg(&g_part[3][bc][1536 + u]);
            float gh = g_gammaH[((size_t)t*B_ + bc)*H_ + u];
            float c1 = sigm(gf)*(gh*c_reg[q]) + sigm(gi)*tanhf(gg);
            float h1 = sigm(go)*tanhf(c1);
            float gtv = sigm(tps[t]*wtr[q] + htr[q]);
            c_reg[q] = gtv*c1;
            stcg(&g_hbuf[p^1][bc][u], gtv*h1);
        }
        gridbar(half, sense);
    }

    // ---- final head: step 127, h in hbuf[0], batch bc ----
    for (int i = tid; i < 512; i += 256)
        h1s[i] = ldcg(&g_hbuf[0][bc][i]);
    __syncthreads();
    {
        int wid = tid >> 5, lane = tid & 31;
        for (int z = wid; z < 10; z += 8) {
            float s = 0.f;
            const float* wv = g_W1T + z*H_;
            #pragma unroll 4
            for (int k = lane; k < H_; k += 32) s = fmaf(h1s[k], __ldg(&wv[k]), s);
            #pragma unroll
            for (int off = 16; off; off >>= 1) s += __shfl_xor_sync(0xffffffffu, s, off);
            if (lane == 0) zs[z] = sigm(s + b1[z]);
        }
        __syncthreads();
        if (tid == 0) {
            float z0 = b2[0], z1 = b2[1];
            #pragma unroll
            for (int j = 0; j < 10; j++) {
                z0 = fmaf(zs[j], W2[j*2 + 0], z0);
                z1 = fmaf(zs[j], W2[j*2 + 1], z1);
            }
            z0 = sigm(z0); z1 = sigm(z1);
            float m = fmaxf(z0, z1);
            float e0 = expf(z0 - m), e1 = expf(z1 - m);
            float inv = 1.f/(e0 + e1);
            out[((size_t)127*B_ + bc)*2 + 0] = e0*inv;
            out[((size_t)127*B_ + bc)*2 + 1] = e1*inv;
        }
    }
}

// ---------------------------------------------------------------------------
extern "C" void kernel_launch(void* const* d_in, const int* in_sizes, int n_in,
                              void* d_out, int out_size)
{
    const float* x     = (const float*)d_in[0];
    const float* dt    = (const float*)d_in[1];
    const float* mask  = (const float*)d_in[2];
    const float* tp    = (const float*)d_in[3];
    const float* xmean = (const float*)d_in[4];
    const float* h0    = (const float*)d_in[5];
    const float* c0    = (const float*)d_in[6];
    const float* wgx   = (const float*)d_in[7];
    const float* hgx   = (const float*)d_in[8];
    const float* wgh   = (const float*)d_in[9];
    const float* hgh   = (const float*)d_in[10];
    const float* wt    = (const float*)d_in[11];
    const float* ht    = (const float*)d_in[12];
    const float* Wih   = (const float*)d_in[13];
    const float* Whh   = (const float*)d_in[14];
    const float* bih   = (const float*)d_in[15];
    const float* bhh   = (const float*)d_in[16];
    const float* W1    = (const float*)d_in[17];
    const float* b1    = (const float*)d_in[18];
    const float* W2    = (const float*)d_in[19];
    const float* b2    = (const float*)d_in[20];
    float* out = (float*)d_out;

    const int PRE_SMEM  = (64 + 128) * LDK * 4;                     // 101,376 B
    const int LOOP_SMEM = (192*LDK + 512 + 16 + 128) * 4;           // 104,000 B
    static bool attr_done = false;
    if (!attr_done) {
        cudaFuncSetAttribute(k_g12, cudaFuncAttributeMaxDynamicSharedMemorySize, PRE_SMEM);
        cudaFuncSetAttribute(k_g3,  cudaFuncAttributeMaxDynamicSharedMemorySize, PRE_SMEM);
        cudaFuncSetAttribute(k_loop, cudaFuncAttributeMaxDynamicSharedMemorySize, LOOP_SMEM);
        attr_done = true;
    }

    k_init<<<B_, H_>>>(h0);
    k_tr<<<778, 256>>>(wgx, wgh, W1);
    k_g12<<<dim3(BT_/64, 6),  256, PRE_SMEM>>>(dt, hgx, hgh, x, mask, xmean, out);
    k_g3<<<dim3(BT_/64, 16), 256, PRE_SMEM>>>(out + XHAT_OFF, Wih, bih, bhh);
    k_loop<<<2*NCTA_HALF, 256, LOOP_SMEM>>>(Whh, c0, tp, wt, ht, b1, W2, b2, out);
}

// round 8
// speedup vs baseline: 1.3375x; 1.0676x over previous
#include <cuda_runtime.h>
#include <cuda_bf16.h>
#include <math.h>
#include <stdint.h>

#define B_ 256
#define T_ 128
#define D_ 256
#define H_ 512
#define BT_ (B_*T_)
#define G4H_ 2048
#define XHAT_OFF (T_*B_*2)   /* outs [T,B,2] first, then xhats [T,B,D] */
#define LDK 132              /* SIMT loop smem row: Kc=128 + 4 pad */
#define NCTA_HALF 128
#define LDF 72               /* bf16 frag-tile row stride: 144B, 16B-aligned, cf */

// ---- device scratch (allocation-free rule) ----
__device__ float g_gammaH[(size_t)T_*B_*H_];      // [T,B,H]
__device__ float g_preGates[(size_t)T_*B_*G4H_];  // [T,B,4H]
__device__ float g_part[4][B_][G4H_];             // split-K partials
__device__ float g_hbuf[2][B_][H_];               // double-buffered h
__device__ float g_wT[(D_+H_)*D_];                // wgxT [256,256] then wghT [512,256]
__device__ float g_W1T[10*H_];                    // W1 transposed [10][512]
__device__ unsigned g_barC[2][32];
__device__ unsigned g_barS[2][32];

typedef unsigned long long u64;
union F2U { u64 u; float2 f; };

__device__ __forceinline__ u64 ffma2(u64 a, u64 b, u64 c) {
    u64 d; asm("fma.rn.f32x2 %0,%1,%2,%3;" : "=l"(d) : "l"(a), "l"(b), "l"(c)); return d;
}
__device__ __forceinline__ float sigm(float x){ return 1.f/(1.f+expf(-x)); }
__device__ __forceinline__ float ldcg(const float* p){
    float v; asm volatile("ld.global.cg.f32 %0,[%1];" : "=f"(v) : "l"(p)); return v;
}
__device__ __forceinline__ float4 ldcg4(const float* p){
    float4 v; asm volatile("ld.global.cg.v4.f32 {%0,%1,%2,%3},[%4];"
        : "=f"(v.x),"=f"(v.y),"=f"(v.z),"=f"(v.w) : "l"(p)); return v;
}
__device__ __forceinline__ void stcg(float* p, float v){
    asm volatile("st.global.cg.f32 [%0],%1;" :: "l"(p), "f"(v));
}
__device__ __forceinline__ uint32_t s2u(const void* p){
    uint32_t a;
    asm("{ .reg .u64 t; cvta.to.shared.u64 t, %1; cvt.u32.u64 %0, t; }" : "=r"(a) : "l"(p));
    return a;
}

// ============================================================================
// HMMA bf16x3 GEMM machinery (mma.sync m16n8k16 — baseline PTX, no 'a' target)
// ============================================================================
__device__ __forceinline__ void ldm4(uint32_t* r, uint32_t addr){
    asm volatile("ldmatrix.sync.aligned.m8n8.x4.shared.b16 {%0,%1,%2,%3}, [%4];"
        : "=r"(r[0]),"=r"(r[1]),"=r"(r[2]),"=r"(r[3]) : "r"(addr));
}
__device__ __forceinline__ void mma_bf16(float* d, const uint32_t* a,
                                         uint32_t b0, uint32_t b1){
    asm volatile("mma.sync.aligned.m16n8k16.row.col.f32.bf16.bf16.f32 "
        "{%0,%1,%2,%3}, {%4,%5,%6,%7}, {%8,%9}, {%0,%1,%2,%3};"
        : "+f"(d[0]), "+f"(d[1]), "+f"(d[2]), "+f"(d[3])
        : "r"(a[0]), "r"(a[1]), "r"(a[2]), "r"(a[3]), "r"(b0), "r"(b1));
}

// Core: acc[2][8][4] (+=) A[128 rows @arow0][256] @ B[128 rows @brow0][256]^T
// smem (bf16): sAhi[128][LDF], sAlo, sBhi, sBlo  (73,728 B total)
__device__ __forceinline__ void hmma_gemm(
    __nv_bfloat16* sm, const float* __restrict__ A, int arow0, int lda,
    const float* __restrict__ Bsrc, int brow0, int ldb, float acc[2][8][4])
{
    __nv_bfloat16 *sAhi = sm, *sAlo = sm + 128*LDF;
    __nv_bfloat16 *sBhi = sm + 2*128*LDF, *sBlo = sm + 3*128*LDF;
    const int tid = threadIdx.x, lane = tid & 31, wid = tid >> 5;
    const int wm = wid & 3, wn = wid >> 2;
    const int g = lane >> 3, r8 = lane & 7;

    for (int ch = 0; ch < 4; ch++) {
        const int k0 = ch*64;
        if (ch) __syncthreads();
        // ---- stage + split fp32 -> bf16 hi/lo ----
        #pragma unroll 4
        for (int i = tid; i < 2048; i += 256) {
            int rr = i >> 4, q = (i & 15) << 2;
            float4 v = *(const float4*)&A[(size_t)(arow0+rr)*lda + k0 + q];
            __nv_bfloat162 h01 = __floats2bfloat162_rn(v.x, v.y);
            __nv_bfloat162 h23 = __floats2bfloat162_rn(v.z, v.w);
            __nv_bfloat162 l01 = __floats2bfloat162_rn(v.x - __bfloat162float(h01.x),
                                                       v.y - __bfloat162float(h01.y));
            __nv_bfloat162 l23 = __floats2bfloat162_rn(v.z - __bfloat162float(h23.x),
                                                       v.w - __bfloat162float(h23.y));
            *(uint2*)&sAhi[rr*LDF + q] = make_uint2(*(uint32_t*)&h01, *(uint32_t*)&h23);
            *(uint2*)&sAlo[rr*LDF + q] = make_uint2(*(uint32_t*)&l01, *(uint32_t*)&l23);
        }
        #pragma unroll 4
        for (int i = tid; i < 2048; i += 256) {
            int rr = i >> 4, q = (i & 15) << 2;
            float4 v = *(const float4*)&Bsrc[(size_t)(brow0+rr)*ldb + k0 + q];
            __nv_bfloat162 h01 = __floats2bfloat162_rn(v.x, v.y);
            __nv_bfloat162 h23 = __floats2bfloat162_rn(v.z, v.w);
            __nv_bfloat162 l01 = __floats2bfloat162_rn(v.x - __bfloat162float(h01.x),
                                                       v.y - __bfloat162float(h01.y));
            __nv_bfloat162 l23 = __floats2bfloat162_rn(v.z - __bfloat162float(h23.x),
                                                       v.w - __bfloat162float(h23.y));
            *(uint2*)&sBhi[rr*LDF + q] = make_uint2(*(uint32_t*)&h01, *(uint32_t*)&h23);
            *(uint2*)&sBlo[rr*LDF + q] = make_uint2(*(uint32_t*)&l01, *(uint32_t*)&l23);
        }
        __syncthreads();
        // ---- compute: 4 k-steps of 16 ----
        #pragma unroll
        for (int ks = 0; ks < 4; ks++) {
            const int kk = ks*16;
            uint32_t ahi[2][4], alo[2][4], bhi[4][4], blo[4][4];
            #pragma unroll
            for (int mi = 0; mi < 2; mi++) {
                int m = wm*32 + mi*16 + (g & 1)*8 + r8;
                int k = kk + (g >> 1)*8;
                ldm4(ahi[mi], s2u(&sAhi[m*LDF + k]));
                ldm4(alo[mi], s2u(&sAlo[m*LDF + k]));
            }
            #pragma unroll
            for (int np = 0; np < 4; np++) {
                int n = wn*64 + np*16 + (g >> 1)*8 + r8;
                int k = kk + (g & 1)*8;
                ldm4(bhi[np], s2u(&sBhi[n*LDF + k]));
                ldm4(blo[np], s2u(&sBlo[n*LDF + k]));
            }
            #pragma unroll
            for (int mi = 0; mi < 2; mi++)
                #pragma unroll
                for (int nj = 0; nj < 8; nj++) {
                    uint32_t h0 = bhi[nj>>1][(nj&1)*2], h1 = bhi[nj>>1][(nj&1)*2+1];
                    uint32_t l0 = blo[nj>>1][(nj&1)*2], l1 = blo[nj>>1][(nj&1)*2+1];
                    mma_bf16(acc[mi][nj], ahi[mi], h0, h1);
                    mma_bf16(acc[mi][nj], ahi[mi], l0, l1);
                    mma_bf16(acc[mi][nj], alo[mi], h0, h1);
                }
        }
    }
}
#define HM_SMEM (4*128*LDF*2)

// ---------------------------------------------------------------------------
// G12 (HMMA): gamma_x (+imputation->xhat) and gamma_h.  grid (BT/128, 6).
//   by<2: gamma_x cols by*128; by>=2: gamma_h cols by*128-256.
// ---------------------------------------------------------------------------
__global__ void __launch_bounds__(256) k_g12_h(
    const float* __restrict__ dt,  const float* __restrict__ hgx,
    const float* __restrict__ hgh, const float* __restrict__ x,
    const float* __restrict__ mask, const float* __restrict__ xmean,
    float* __restrict__ out)
{
    extern __shared__ __nv_bfloat16 smb[];
    float acc[2][8][4] = {};
    const int m0 = blockIdx.x*128, n0 = blockIdx.y*128;
    hmma_gemm(smb, dt, m0, D_, (const float*)g_wT, n0, D_, acc);

    const int lane = threadIdx.x & 31, wid = threadIdx.x >> 5;
    const int wm = wid & 3, wn = wid >> 2;
    const int tg = lane >> 2, tc = (lane & 3)*2;

    #pragma unroll
    for (int mi = 0; mi < 2; mi++) {
        #pragma unroll
        for (int nj = 0; nj < 8; nj++) {
            const float* a4 = acc[mi][nj];
            int ng = n0 + wn*64 + nj*8 + tc;
            #pragma unroll
            for (int h = 0; h < 2; h++) {
                int row = m0 + wm*32 + mi*16 + tg + h*8;   // = b*T + t
                int b = row >> 7, t = row & (T_-1);
                float v0 = a4[h*2], v1 = a4[h*2+1];
                if (blockIdx.y < 2) {
                    int d = ng;
                    float o[2];
                    #pragma unroll
                    for (int e = 0; e < 2; e++) {
                        float v = e ? v1 : v0; int dd = d + e;
                        float gm = expf(-fmaxf(v + hgx[dd], 0.f));
                        float mv = mask[(size_t)row*D_ + dd];
                        float xt = x[(size_t)row*D_ + dd];
                        float xm = xmean[dd];
                        float imp = (t == 0) ? xm
                                  : fmaf(gm, x[(size_t)(row-1)*D_ + dd], (1.f-gm)*xm);
                        o[e] = xt*mv + (1.f-mv)*imp;
                    }
                    *(float2*)&out[XHAT_OFF + ((size_t)t*B_ + b)*D_ + d] = make_float2(o[0], o[1]);
                } else {
                    int u = ng - 256;
                    float2 o;
                    o.x = expf(-fmaxf(v0 + hgh[u],   0.f));
                    o.y = expf(-fmaxf(v1 + hgh[u+1], 0.f));
                    *(float2*)&g_gammaH[((size_t)t*B_ + b)*H_ + u] = o;
                }
            }
        }
    }
}

// ---------------------------------------------------------------------------
// G3 (HMMA): pre_gates = xs @ W_ih^T + b_ih + b_hh.  grid (BT/128, 16).
// ---------------------------------------------------------------------------
__global__ void __launch_bounds__(256) k_g3_h(
    const float* __restrict__ xsrc, const float* __restrict__ Wih,
    const float* __restrict__ bih,  const float* __restrict__ bhh)
{
    extern __shared__ __nv_bfloat16 smb[];
    float acc[2][8][4] = {};
    const int m0 = blockIdx.x*128, n0 = blockIdx.y*128;
    hmma_gemm(smb, xsrc, m0, D_, Wih, n0, D_, acc);

    const int lane = threadIdx.x & 31, wid = threadIdx.x >> 5;
    const int wm = wid & 3, wn = wid >> 2;
    const int tg = lane >> 2, tc = (lane & 3)*2;

    #pragma unroll
    for (int mi = 0; mi < 2; mi++) {
        #pragma unroll
        for (int nj = 0; nj < 8; nj++) {
            const float* a4 = acc[mi][nj];
            int n = n0 + wn*64 + nj*8 + tc;
            float bi0 = bih[n] + bhh[n], bi1 = bih[n+1] + bhh[n+1];
            #pragma unroll
            for (int h = 0; h < 2; h++) {
                int row = m0 + wm*32 + mi*16 + tg + h*8;   // = t*B + b
                *(float2*)&g_preGates[(size_t)row*G4H_ + n] =
                    make_float2(a4[h*2] + bi0, a4[h*2+1] + bi1);
            }
        }
    }
}

// ============================================================================
// SIMT persistent recurrent loop (unchanged from passing R6 kernel)
// ============================================================================
__device__ __forceinline__ void mm64(const float* __restrict__ As,
                                     const float* __restrict__ Bs,
                                     u64 acc[4][8], int tx, int ty)
{
    #pragma unroll 1
    for (int k4 = 0; k4 < 32; k4++) {
        float4 a4[4], w4[8];
        #pragma unroll
        for (int i = 0; i < 4; i++) a4[i] = *(const float4*)&As[(ty+16*i)*LDK + 4*k4];
        #pragma unroll
        for (int j = 0; j < 8; j++) w4[j] = *(const float4*)&Bs[(tx+16*j)*LDK + 4*k4];
        #pragma unroll
        for (int i = 0; i < 4; i++) {
            u64 alo = ((const u64*)&a4[i])[0], ahi = ((const u64*)&a4[i])[1];
            #pragma unroll
            for (int j = 0; j < 8; j++) {
                acc[i][j] = ffma2(alo, ((const u64*)&w4[j])[0], acc[i][j]);
                acc[i][j] = ffma2(ahi, ((const u64*)&w4[j])[1], acc[i][j]);
            }
        }
    }
}

__device__ __forceinline__ void load_tile(float* dst, const float* src,
                                          int rows, int row0, int ld, int col0)
{
    for (int i = threadIdx.x; i < rows*32; i += 256) {
        int r = i >> 5, q = (i & 31) << 2;
        *(float4*)&dst[r*LDK + q] = *(const float4*)&src[(size_t)(row0+r)*ld + col0 + q];
    }
}

__global__ void __launch_bounds__(H_) k_init(const float* __restrict__ h0)
{
    g_hbuf[0][blockIdx.x][threadIdx.x] = h0[threadIdx.x];
}

__global__ void __launch_bounds__(256) k_tr(const float* __restrict__ wgx,
                                            const float* __restrict__ wgh,
                                            const float* __restrict__ W1)
{
    int blk = blockIdx.x, k = threadIdx.x;
    if (blk < 256) g_wT[blk*D_ + k] = wgx[k*D_ + blk];
    else if (blk < 768) { int n = blk - 256; g_wT[D_*D_ + n*D_ + k] = wgh[k*H_ + n]; }
    else {
        int z = blk - 768;
        g_W1T[z*H_ + k]       = W1[k*10 + z];
        g_W1T[z*H_ + k + 256] = W1[(k+256)*10 + z];
    }
}

__device__ __forceinline__ void gridbar(int half, unsigned &sense)
{
    __syncthreads();
    if (threadIdx.x == 0) {
        unsigned s = sense ^ 1, old;
        asm volatile("atom.acq_rel.gpu.global.add.u32 %0,[%1],1;"
                     : "=r"(old) : "l"(&g_barC[half][0]));
        if (old == NCTA_HALF-1) {
            asm volatile("st.relaxed.gpu.global.u32 [%0],%1;" :: "l"(&g_barC[half][0]), "r"(0u));
            asm volatile("st.release.gpu.global.u32 [%0],%1;" :: "l"(&g_barS[half][0]), "r"(s));
        } else {
            unsigned v;
            do {
                asm volatile("ld.acquire.gpu.global.u32 %0,[%1];" : "=r"(v) : "l"(&g_barS[half][0]));
            } while (v != s);
        }
    }
    __syncthreads();
    sense ^= 1;
}

__global__ void __launch_bounds__(256,2) k_loop(
    const float* __restrict__ Whh, const float* __restrict__ c0,
    const float* __restrict__ tp,  const float* __restrict__ wt,
    const float* __restrict__ ht,  const float* __restrict__ b1,
    const float* __restrict__ W2,  const float* __restrict__ b2,
    float* __restrict__ out)
{
    extern __shared__ float sm[];
    float *Wsm = sm;
    float *ahs = sm + 128*LDK;
    float *h1s = sm + 192*LDK;
    float *zs  = h1s + 512;
    float *tps = zs + 16;

    const int tid = threadIdx.x;
    const int half  = (blockIdx.x < 128) ? 0 : 1;
    const int local = blockIdx.x - half*128;
    const int kb = local & 3, nb = (local >> 2) & 15, mb = local >> 6;
    const int b0 = half*128 + mb*64, c0i = nb*128, k0 = kb*128;
    const int bc = half*128 + local;
    const int tx = tid & 15, ty = tid >> 4;
    unsigned sense = 0;

    load_tile(Wsm, Whh, 128, c0i, H_, k0);
    for (int i = tid; i < 128; i += 256) tps[i] = tp[bc*T_ + i];

    float c_reg[2], wtr[2], htr[2];
    #pragma unroll
    for (int q = 0; q < 2; q++) {
        c_reg[q] = c0[tid + 256*q];
        wtr[q]   = wt[tid + 256*q];
        htr[q]   = ht[tid + 256*q];
    }
    __syncthreads();

    for (int t = 0; t < T_; t++) {
        const int p = t & 1;

        if (t > 0)
            for (int i = tid; i < 512; i += 256)
                h1s[i] = ldcg(&g_hbuf[p][bc][i]);
        for (int i = tid; i < 64*32; i += 256) {
            int r = i >> 5, q = (i & 31) << 2;
            int bg = b0 + r;
            float4 g = *(const float4*)&g_gammaH[((size_t)t*B_ + bg)*H_ + k0 + q];
            float4 h = ldcg4(&g_hbuf[p][bg][k0 + q]);
            g.x *= h.x; g.y *= h.y; g.z *= h.z; g.w *= h.w;
            *(float4*)&ahs[r*LDK + q] = g;
        }
        __syncthreads();

        if (t > 0) {
            int wid = tid >> 5, lane = tid & 31;
            for (int z = wid; z < 10; z += 8) {
                float s = 0.f;
                const float* wv = g_W1T + z*H_;
                #pragma unroll 4
                for (int k = lane; k < H_; k += 32) s = fmaf(h1s[k], __ldg(&wv[k]), s);
                #pragma unroll
                for (int off = 16; off; off >>= 1) s += __shfl_xor_sync(0xffffffffu, s, off);
                if (lane == 0) zs[z] = sigm(s + b1[z]);
            }
            __syncthreads();
            if (tid == 0) {
                float z0 = b2[0], z1 = b2[1];
                #pragma unroll
                for (int j = 0; j < 10; j++) {
                    z0 = fmaf(zs[j], W2[j*2 + 0], z0);
                    z1 = fmaf(zs[j], W2[j*2 + 1], z1);
                }
                z0 = sigm(z0); z1 = sigm(z1);
                float m = fmaxf(z0, z1);
                float e0 = expf(z0 - m), e1 = expf(z1 - m);
                float inv = 1.f/(e0 + e1);
                out[((size_t)(t-1)*B_ + bc)*2 + 0] = e0*inv;
                out[((size_t)(t-1)*B_ + bc)*2 + 1] = e1*inv;
            }
        }

        u64 acc[4][8] = {};
        mm64(ahs, Wsm, acc, tx, ty);
        #pragma unroll
        for (int i = 0; i < 4; i++) {
            int bg = b0 + ty + 16*i;
            #pragma unroll
            for (int j = 0; j < 8; j++) {
                F2U v; v.u = acc[i][j];
                stcg(&g_part[kb][bg][c0i + tx + 16*j], v.f.x + v.f.y);
            }
        }
        gridbar(half, sense);

        #pragma unroll
        for (int q = 0; q < 2; q++) {
            int u = tid + 256*q;
            const float* pre = &g_preGates[((size_t)t*B_ + bc)*G4H_];
            float gi = pre[u]        + ldcg(&g_part[0][bc][u])        + ldcg(&g_part[1][bc][u])
                                     + ldcg(&g_part[2][bc][u])        + ldcg(&g_part[3][bc][u]);
            float gf = pre[512 + u]  + ldcg(&g_part[0][bc][512 + u])  + ldcg(&g_part[1][bc][512 + u])
                                     + ldcg(&g_part[2][bc][512 + u])  + ldcg(&g_part[3][bc][512 + u]);
            float gg = pre[1024 + u] + ldcg(&g_part[0][bc][1024 + u]) + ldcg(&g_part[1][bc][1024 + u])
                                     + ldcg(&g_part[2][bc][1024 + u]) + ldcg(&g_part[3][bc][1024 + u]);
            float go = pre[1536 + u] + ldcg(&g_part[0][bc][1536 + u]) + ldcg(&g_part[1][bc][1536 + u])
                                     + ldcg(&g_part[2][bc][1536 + u]) + ldcg(&g_part[3][bc][1536 + u]);
            float gh = g_gammaH[((size_t)t*B_ + bc)*H_ + u];
            float c1 = sigm(gf)*(gh*c_reg[q]) + sigm(gi)*tanhf(gg);
            float h1 = sigm(go)*tanhf(c1);
            float gtv = sigm(tps[t]*wtr[q] + htr[q]);
            c_reg[q] = gtv*c1;
            stcg(&g_hbuf[p^1][bc][u], gtv*h1);
        }
        gridbar(half, sense);
    }

    for (int i = tid; i < 512; i += 256)
        h1s[i] = ldcg(&g_hbuf[0][bc][i]);
    __syncthreads();
    {
        int wid = tid >> 5, lane = tid & 31;
        for (int z = wid; z < 10; z += 8) {
            float s = 0.f;
            const float* wv = g_W1T + z*H_;
            #pragma unroll 4
            for (int k = lane; k < H_; k += 32) s = fmaf(h1s[k], __ldg(&wv[k]), s);
            #pragma unroll
            for (int off = 16; off; off >>= 1) s += __shfl_xor_sync(0xffffffffu, s, off);
            if (lane == 0) zs[z] = sigm(s + b1[z]);
        }
        __syncthreads();
        if (tid == 0) {
            float z0 = b2[0], z1 = b2[1];
            #pragma unroll
            for (int j = 0; j < 10; j++) {
                z0 = fmaf(zs[j], W2[j*2 + 0], z0);
                z1 = fmaf(zs[j], W2[j*2 + 1], z1);
            }
            z0 = sigm(z0); z1 = sigm(z1);
            float m = fmaxf(z0, z1);
            float e0 = expf(z0 - m), e1 = expf(z1 - m);
            float inv = 1.f/(e0 + e1);
            out[((size_t)127*B_ + bc)*2 + 0] = e0*inv;
            out[((size_t)127*B_ + bc)*2 + 1] = e1*inv;
        }
    }
}

// ---------------------------------------------------------------------------
extern "C" void kernel_launch(void* const* d_in, const int* in_sizes, int n_in,
                              void* d_out, int out_size)
{
    const float* x     = (const float*)d_in[0];
    const float* dt    = (const float*)d_in[1];
    const float* mask  = (const float*)d_in[2];
    const float* tp    = (const float*)d_in[3];
    const float* xmean = (const float*)d_in[4];
    const float* h0    = (const float*)d_in[5];
    const float* c0    = (const float*)d_in[6];
    const float* wgx   = (const float*)d_in[7];
    const float* hgx   = (const float*)d_in[8];
    const float* wgh   = (const float*)d_in[9];
    const float* hgh   = (const float*)d_in[10];
    const float* wt    = (const float*)d_in[11];
    const float* ht    = (const float*)d_in[12];
    const float* Wih   = (const float*)d_in[13];
    const float* Whh   = (const float*)d_in[14];
    const float* bih   = (const float*)d_in[15];
    const float* bhh   = (const float*)d_in[16];
    const float* W1    = (const float*)d_in[17];
    const float* b1    = (const float*)d_in[18];
    const float* W2    = (const float*)d_in[19];
    const float* b2    = (const float*)d_in[20];
    float* out = (float*)d_out;

    const int LOOP_SMEM = (192*LDK + 512 + 16 + 128) * 4;
    static bool attr_done = false;
    if (!attr_done) {
        cudaFuncSetAttribute(k_g12_h, cudaFuncAttributeMaxDynamicSharedMemorySize, HM_SMEM);
        cudaFuncSetAttribute(k_g3_h,  cudaFuncAttributeMaxDynamicSharedMemorySize, HM_SMEM);
        cudaFuncSetAttribute(k_loop,  cudaFuncAttributeMaxDynamicSharedMemorySize, LOOP_SMEM);
        attr_done = true;
    }

    k_init<<<B_, H_>>>(h0);
    k_tr<<<778, 256>>>(wgx, wgh, W1);
    k_g12_h<<<dim3(BT_/128, 6),  256, HM_SMEM>>>(dt, hgx, hgh, x, mask, xmean, out);
    k_g3_h<<<dim3(BT_/128, 16), 256, HM_SMEM>>>(out + XHAT_OFF, Wih, bih, bhh);
    k_loop<<<2*NCTA_HALF, 256, LOOP_SMEM>>>(Whh, c0, tp, wt, ht, b1, W2, b2, out);
}

// round 10
// speedup vs baseline: 1.4767x; 1.1040x over previous
#include <cuda_runtime.h>
#include <cuda_bf16.h>
#include <math.h>
#include <stdint.h>

#define B_ 256
#define T_ 128
#define D_ 256
#define H_ 512
#define BT_ (B_*T_)
#define G4H_ 2048
#define XHAT_OFF (T_*B_*2)   /* outs [T,B,2] first, then xhats [T,B,D] */
#define LDK 132              /* SIMT loop smem row: Kc=128 + 4 pad */
#define NCTA_GROUP 64        /* loop: 4 independent groups of 64 CTAs */
#define LDF 72               /* bf16 frag-tile row stride: 144B, 16B-aligned, cf */

// ---- device scratch (allocation-free rule) ----
__device__ float g_gammaH[(size_t)T_*B_*H_];      // [T,B,H]
__device__ float g_preGates[(size_t)T_*B_*G4H_];  // [T,B,4H]
__device__ float g_part[4][B_][G4H_];             // split-K partials
__device__ float g_hbuf[2][B_][H_];               // double-buffered h
__device__ float g_wT[(D_+H_)*D_];                // wgxT [256,256] then wghT [512,256]
__device__ float g_W1T[10*H_];                    // W1 transposed [10][512]
__device__ unsigned g_barC[4][32];                // per-group barrier counter
__device__ unsigned g_barS[4][32];                // per-group barrier flag

typedef unsigned long long u64;
union F2U { u64 u; float2 f; };

__device__ __forceinline__ u64 ffma2(u64 a, u64 b, u64 c) {
    u64 d; asm("fma.rn.f32x2 %0,%1,%2,%3;" : "=l"(d) : "l"(a), "l"(b), "l"(c)); return d;
}
__device__ __forceinline__ float sigm(float x){ return 1.f/(1.f+expf(-x)); }
__device__ __forceinline__ float ldcg(const float* p){
    float v; asm volatile("ld.global.cg.f32 %0,[%1];" : "=f"(v) : "l"(p)); return v;
}
__device__ __forceinline__ float4 ldcg4(const float* p){
    float4 v; asm volatile("ld.global.cg.v4.f32 {%0,%1,%2,%3},[%4];"
        : "=f"(v.x),"=f"(v.y),"=f"(v.z),"=f"(v.w) : "l"(p)); return v;
}
__device__ __forceinline__ void stcg(float* p, float v){
    asm volatile("st.global.cg.f32 [%0],%1;" :: "l"(p), "f"(v));
}
__device__ __forceinline__ uint32_t s2u(const void* p){
    uint32_t a;
    asm("{ .reg .u64 t; cvta.to.shared.u64 t, %1; cvt.u32.u64 %0, t; }" : "=r"(a) : "l"(p));
    return a;
}

// ============================================================================
// HMMA bf16x3 GEMM machinery (mma.sync m16n8k16) — pre-GEMMs only.
// ============================================================================
__device__ __forceinline__ void ldm4(uint32_t* r, uint32_t addr){
    asm volatile("ldmatrix.sync.aligned.m8n8.x4.shared.b16 {%0,%1,%2,%3}, [%4];"
        : "=r"(r[0]),"=r"(r[1]),"=r"(r[2]),"=r"(r[3]) : "r"(addr));
}
__device__ __forceinline__ void mma_bf16(float* d, const uint32_t* a,
                                         uint32_t b0, uint32_t b1){
    asm volatile("mma.sync.aligned.m16n8k16.row.col.f32.bf16.bf16.f32 "
        "{%0,%1,%2,%3}, {%4,%5,%6,%7}, {%8,%9}, {%0,%1,%2,%3};"
        : "+f"(d[0]), "+f"(d[1]), "+f"(d[2]), "+f"(d[3])
        : "r"(a[0]), "r"(a[1]), "r"(a[2]), "r"(a[3]), "r"(b0), "r"(b1));
}
__device__ __forceinline__ void split4(float4 v, uint2& hi, uint2& lo){
    __nv_bfloat162 h01 = __floats2bfloat162_rn(v.x, v.y);
    __nv_bfloat162 h23 = __floats2bfloat162_rn(v.z, v.w);
    __nv_bfloat162 l01 = __floats2bfloat162_rn(v.x - __bfloat162float(h01.x),
                                               v.y - __bfloat162float(h01.y));
    __nv_bfloat162 l23 = __floats2bfloat162_rn(v.z - __bfloat162float(h23.x),
                                               v.w - __bfloat162float(h23.y));
    hi = make_uint2(*(uint32_t*)&h01, *(uint32_t*)&h23);
    lo = make_uint2(*(uint32_t*)&l01, *(uint32_t*)&l23);
}

// Pre-GEMM core: acc[2][8][4] += A[128 @arow0][256] @ B[128 @brow0][256]^T
__device__ __forceinline__ void hmma_gemm(
    __nv_bfloat16* sm, const float* __restrict__ A, int arow0, int lda,
    const float* __restrict__ Bsrc, int brow0, int ldb, float acc[2][8][4])
{
    __nv_bfloat16 *sAhi = sm, *sAlo = sm + 128*LDF;
    __nv_bfloat16 *sBhi = sm + 2*128*LDF, *sBlo = sm + 3*128*LDF;
    const int tid = threadIdx.x, lane = tid & 31, wid = tid >> 5;
    const int wm = wid & 3, wn = wid >> 2;
    const int g = lane >> 3, r8 = lane & 7;

    for (int ch = 0; ch < 4; ch++) {
        const int k0 = ch*64;
        if (ch) __syncthreads();
        #pragma unroll 4
        for (int i = tid; i < 2048; i += 256) {
            int rr = i >> 4, q = (i & 15) << 2;
            uint2 hi, lo;
            split4(*(const float4*)&A[(size_t)(arow0+rr)*lda + k0 + q], hi, lo);
            *(uint2*)&sAhi[rr*LDF + q] = hi;
            *(uint2*)&sAlo[rr*LDF + q] = lo;
        }
        #pragma unroll 4
        for (int i = tid; i < 2048; i += 256) {
            int rr = i >> 4, q = (i & 15) << 2;
            uint2 hi, lo;
            split4(*(const float4*)&Bsrc[(size_t)(brow0+rr)*ldb + k0 + q], hi, lo);
            *(uint2*)&sBhi[rr*LDF + q] = hi;
            *(uint2*)&sBlo[rr*LDF + q] = lo;
        }
        __syncthreads();
        #pragma unroll
        for (int ks = 0; ks < 4; ks++) {
            const int kk = ks*16;
            uint32_t ahi[2][4], alo[2][4], bhi[4][4], blo[4][4];
            #pragma unroll
            for (int mi = 0; mi < 2; mi++) {
                int m = wm*32 + mi*16 + (g & 1)*8 + r8;
                int k = kk + (g >> 1)*8;
                ldm4(ahi[mi], s2u(&sAhi[m*LDF + k]));
                ldm4(alo[mi], s2u(&sAlo[m*LDF + k]));
            }
            #pragma unroll
            for (int np = 0; np < 4; np++) {
                int n = wn*64 + np*16 + (g >> 1)*8 + r8;
                int k = kk + (g & 1)*8;
                ldm4(bhi[np], s2u(&sBhi[n*LDF + k]));
                ldm4(blo[np], s2u(&sBlo[n*LDF + k]));
            }
            #pragma unroll
            for (int mi = 0; mi < 2; mi++)
                #pragma unroll
                for (int nj = 0; nj < 8; nj++) {
                    uint32_t h0 = bhi[nj>>1][(nj&1)*2], h1 = bhi[nj>>1][(nj&1)*2+1];
                    uint32_t l0 = blo[nj>>1][(nj&1)*2], l1 = blo[nj>>1][(nj&1)*2+1];
                    mma_bf16(acc[mi][nj], ahi[mi], h0, h1);
                    mma_bf16(acc[mi][nj], ahi[mi], l0, l1);
                    mma_bf16(acc[mi][nj], alo[mi], h0, h1);
                }
        }
    }
}
#define HM_SMEM (4*128*LDF*2)

// ---------------------------------------------------------------------------
// G12 (HMMA): gamma_x (+imputation->xhat) and gamma_h.  grid (BT/128, 6).
// ---------------------------------------------------------------------------
__global__ void __launch_bounds__(256,2) k_g12_h(
    const float* __restrict__ dt,  const float* __restrict__ hgx,
    const float* __restrict__ hgh, const float* __restrict__ x,
    const float* __restrict__ mask, const float* __restrict__ xmean,
    float* __restrict__ out)
{
    extern __shared__ __nv_bfloat16 smb[];
    float acc[2][8][4] = {};
    const int m0 = blockIdx.x*128, n0 = blockIdx.y*128;
    hmma_gemm(smb, dt, m0, D_, (const float*)g_wT, n0, D_, acc);

    const int lane = threadIdx.x & 31, wid = threadIdx.x >> 5;
    const int wm = wid & 3, wn = wid >> 2;
    const int tg = lane >> 2, tc = (lane & 3)*2;

    #pragma unroll
    for (int mi = 0; mi < 2; mi++) {
        #pragma unroll
        for (int nj = 0; nj < 8; nj++) {
            const float* a4 = acc[mi][nj];
            int ng = n0 + wn*64 + nj*8 + tc;
            #pragma unroll
            for (int h = 0; h < 2; h++) {
                int row = m0 + wm*32 + mi*16 + tg + h*8;   // = b*T + t
                int b = row >> 7, t = row & (T_-1);
                float v0 = a4[h*2], v1 = a4[h*2+1];
                if (blockIdx.y < 2) {
                    int d = ng;
                    float o[2];
                    #pragma unroll
                    for (int e = 0; e < 2; e++) {
                        float v = e ? v1 : v0; int dd = d + e;
                        float gm = expf(-fmaxf(v + hgx[dd], 0.f));
                        float mv = mask[(size_t)row*D_ + dd];
                        float xt = x[(size_t)row*D_ + dd];
                        float xm = xmean[dd];
                        float imp = (t == 0) ? xm
                                  : fmaf(gm, x[(size_t)(row-1)*D_ + dd], (1.f-gm)*xm);
                        o[e] = xt*mv + (1.f-mv)*imp;
                    }
                    *(float2*)&out[XHAT_OFF + ((size_t)t*B_ + b)*D_ + d] = make_float2(o[0], o[1]);
                } else {
                    int u = ng - 256;
                    float2 o;
                    o.x = expf(-fmaxf(v0 + hgh[u],   0.f));
                    o.y = expf(-fmaxf(v1 + hgh[u+1], 0.f));
                    *(float2*)&g_gammaH[((size_t)t*B_ + b)*H_ + u] = o;
                }
            }
        }
    }
}

// ---------------------------------------------------------------------------
// G3 (HMMA): pre_gates = xs @ W_ih^T + b_ih + b_hh.  grid (BT/128, 16).
// ---------------------------------------------------------------------------
__global__ void __launch_bounds__(256,2) k_g3_h(
    const float* __restrict__ xsrc, const float* __restrict__ Wih,
    const float* __restrict__ bih,  const float* __restrict__ bhh)
{
    extern __shared__ __nv_bfloat16 smb[];
    float acc[2][8][4] = {};
    const int m0 = blockIdx.x*128, n0 = blockIdx.y*128;
    hmma_gemm(smb, xsrc, m0, D_, Wih, n0, D_, acc);

    const int lane = threadIdx.x & 31, wid = threadIdx.x >> 5;
    const int wm = wid & 3, wn = wid >> 2;
    const int tg = lane >> 2, tc = (lane & 3)*2;

    #pragma unroll
    for (int mi = 0; mi < 2; mi++) {
        #pragma unroll
        for (int nj = 0; nj < 8; nj++) {
            const float* a4 = acc[mi][nj];
            int n = n0 + wn*64 + nj*8 + tc;
            float bi0 = bih[n] + bhh[n], bi1 = bih[n+1] + bhh[n+1];
            #pragma unroll
            for (int h = 0; h < 2; h++) {
                int row = m0 + wm*32 + mi*16 + tg + h*8;   // = t*B + b
                *(float2*)&g_preGates[(size_t)row*G4H_ + n] =
                    make_float2(a4[h*2] + bi0, a4[h*2+1] + bi1);
            }
        }
    }
}

// ============================================================================
// SIMT persistent recurrent loop (fp32 FFMA2 — exact; R8-proven numerics)
// ============================================================================
__device__ __forceinline__ void mm64(const float* __restrict__ As,
                                     const float* __restrict__ Bs,
                                     u64 acc[4][8], int tx, int ty)
{
    #pragma unroll 1
    for (int k4 = 0; k4 < 32; k4++) {
        float4 a4[4], w4[8];
        #pragma unroll
        for (int i = 0; i < 4; i++) a4[i] = *(const float4*)&As[(ty+16*i)*LDK + 4*k4];
        #pragma unroll
        for (int j = 0; j < 8; j++) w4[j] = *(const float4*)&Bs[(tx+16*j)*LDK + 4*k4];
        #pragma unroll
        for (int i = 0; i < 4; i++) {
            u64 alo = ((const u64*)&a4[i])[0], ahi = ((const u64*)&a4[i])[1];
            #pragma unroll
            for (int j = 0; j < 8; j++) {
                acc[i][j] = ffma2(alo, ((const u64*)&w4[j])[0], acc[i][j]);
                acc[i][j] = ffma2(ahi, ((const u64*)&w4[j])[1], acc[i][j]);
            }
        }
    }
}

__device__ __forceinline__ void load_tile(float* dst, const float* src,
                                          int rows, int row0, int ld, int col0)
{
    for (int i = threadIdx.x; i < rows*32; i += 256) {
        int r = i >> 5, q = (i & 31) << 2;
        *(float4*)&dst[r*LDK + q] = *(const float4*)&src[(size_t)(row0+r)*ld + col0 + q];
    }
}

__global__ void __launch_bounds__(H_) k_init(const float* __restrict__ h0)
{
    g_hbuf[0][blockIdx.x][threadIdx.x] = h0[threadIdx.x];
}

__global__ void __launch_bounds__(256) k_tr(const float* __restrict__ wgx,
                                            const float* __restrict__ wgh,
                                            const float* __restrict__ W1)
{
    int blk = blockIdx.x, k = threadIdx.x;
    if (blk < 256) g_wT[blk*D_ + k] = wgx[k*D_ + blk];
    else if (blk < 768) { int n = blk - 256; g_wT[D_*D_ + n*D_ + k] = wgh[k*H_ + n]; }
    else {
        int z = blk - 768;
        g_W1T[z*H_ + k]       = W1[k*10 + z];
        g_W1T[z*H_ + k + 256] = W1[(k+256)*10 + z];
    }
}

// per-group grid barrier (64 CTAs). 256 passes/launch -> replay-safe.
__device__ __forceinline__ void gridbar(int grp, unsigned &sense)
{
    __syncthreads();
    if (threadIdx.x == 0) {
        unsigned s = sense ^ 1, old;
        asm volatile("atom.acq_rel.gpu.global.add.u32 %0,[%1],1;"
                     : "=r"(old) : "l"(&g_barC[grp][0]));
        if (old == NCTA_GROUP-1) {
            asm volatile("st.relaxed.gpu.global.u32 [%0],%1;" :: "l"(&g_barC[grp][0]), "r"(0u));
            asm volatile("st.release.gpu.global.u32 [%0],%1;" :: "l"(&g_barS[grp][0]), "r"(s));
        } else {
            unsigned v;
            do {
                asm volatile("ld.acquire.gpu.global.u32 %0,[%1];" : "=r"(v) : "l"(&g_barS[grp][0]));
            } while (v != s);
        }
    }
    __syncthreads();
    sense ^= 1;
}

// ---------------------------------------------------------------------------
// Persistent loop: 256 CTAs in 4 independent groups of 64 (all deps close
// within (half, mb) groups). CTA = (kb,nb,mb,half):
//   tile b[b0,+64) x c[c0i,+128) x k[k0,+128); cell batch bc = half*128+local.
// ---------------------------------------------------------------------------
__global__ void __launch_bounds__(256,2) k_loop(
    const float* __restrict__ Whh, const float* __restrict__ c0,
    const float* __restrict__ tp,  const float* __restrict__ wt,
    const float* __restrict__ ht,  const float* __restrict__ b1,
    const float* __restrict__ W2,  const float* __restrict__ b2,
    float* __restrict__ out)
{
    extern __shared__ float sm[];
    float *Wsm = sm;
    float *ahs = sm + 128*LDK;
    float *h1s = sm + 192*LDK;
    float *zs  = h1s + 512;
    float *tps = zs + 16;

    const int tid = threadIdx.x;
    const int half  = blockIdx.x >> 7;
    const int local = blockIdx.x & 127;
    const int grp   = blockIdx.x >> 6;           // (half, mb) group, 0..3
    const int kb = local & 3, nb = (local >> 2) & 15, mb = local >> 6;
    const int b0 = half*128 + mb*64, c0i = nb*128, k0 = kb*128;
    const int bc = half*128 + local;
    const int tx = tid & 15, ty = tid >> 4;
    unsigned sense = 0;

    load_tile(Wsm, Whh, 128, c0i, H_, k0);
    for (int i = tid; i < 128; i += 256) tps[i] = tp[bc*T_ + i];

    float c_reg[2], wtr[2], htr[2];
    #pragma unroll
    for (int q = 0; q < 2; q++) {
        c_reg[q] = c0[tid + 256*q];
        wtr[q]   = wt[tid + 256*q];
        htr[q]   = ht[tid + 256*q];
    }
    __syncthreads();

    for (int t = 0; t < T_; t++) {
        const int p = t & 1;

        if (t > 0)
            for (int i = tid; i < 512; i += 256)
                h1s[i] = ldcg(&g_hbuf[p][bc][i]);
        for (int i = tid; i < 64*32; i += 256) {
            int r = i >> 5, q = (i & 31) << 2;
            int bg = b0 + r;
            float4 g = *(const float4*)&g_gammaH[((size_t)t*B_ + bg)*H_ + k0 + q];
            float4 h = ldcg4(&g_hbuf[p][bg][k0 + q]);
            g.x *= h.x; g.y *= h.y; g.z *= h.z; g.w *= h.w;
            *(float4*)&ahs[r*LDK + q] = g;
        }
        __syncthreads();

        if (t > 0) {
            int wid = tid >> 5, lane = tid & 31;
            for (int z = wid; z < 10; z += 8) {
                float s = 0.f;
                const float* wv = g_W1T + z*H_;
                #pragma unroll 4
                for (int k = lane; k < H_; k += 32) s = fmaf(h1s[k], __ldg(&wv[k]), s);
                #pragma unroll
                for (int off = 16; off; off >>= 1) s += __shfl_xor_sync(0xffffffffu, s, off);
                if (lane == 0) zs[z] = sigm(s + b1[z]);
            }
            __syncthreads();
            if (tid == 0) {
                float z0 = b2[0], z1 = b2[1];
                #pragma unroll
                for (int j = 0; j < 10; j++) {
                    z0 = fmaf(zs[j], W2[j*2 + 0], z0);
                    z1 = fmaf(zs[j], W2[j*2 + 1], z1);
                }
                z0 = sigm(z0); z1 = sigm(z1);
                float m = fmaxf(z0, z1);
                float e0 = expf(z0 - m), e1 = expf(z1 - m);
                float inv = 1.f/(e0 + e1);
                out[((size_t)(t-1)*B_ + bc)*2 + 0] = e0*inv;
                out[((size_t)(t-1)*B_ + bc)*2 + 1] = e1*inv;
            }
        }

        u64 acc[4][8] = {};
        mm64(ahs, Wsm, acc, tx, ty);
        #pragma unroll
        for (int i = 0; i < 4; i++) {
            int bg = b0 + ty + 16*i;
            #pragma unroll
            for (int j = 0; j < 8; j++) {
                F2U v; v.u = acc[i][j];
                stcg(&g_part[kb][bg][c0i + tx + 16*j], v.f.x + v.f.y);
            }
        }
        gridbar(grp, sense);

        #pragma unroll
        for (int q = 0; q < 2; q++) {
            int u = tid + 256*q;
            const float* pre = &g_preGates[((size_t)t*B_ + bc)*G4H_];
            float gi = pre[u]        + ldcg(&g_part[0][bc][u])        + ldcg(&g_part[1][bc][u])
                                     + ldcg(&g_part[2][bc][u])        + ldcg(&g_part[3][bc][u]);
            float gf = pre[512 + u]  + ldcg(&g_part[0][bc][512 + u])  + ldcg(&g_part[1][bc][512 + u])
                                     + ldcg(&g_part[2][bc][512 + u])  + ldcg(&g_part[3][bc][512 + u]);
            float gg = pre[1024 + u] + ldcg(&g_part[0][bc][1024 + u]) + ldcg(&g_part[1][bc][1024 + u])
                                     + ldcg(&g_part[2][bc][1024 + u]) + ldcg(&g_part[3][bc][1024 + u]);
            float go = pre[1536 + u] + ldcg(&g_part[0][bc][1536 + u]) + ldcg(&g_part[1][bc][1536 + u])
                                     + ldcg(&g_part[2][bc][1536 + u]) + ldcg(&g_part[3][bc][1536 + u]);
            float gh = g_gammaH[((size_t)t*B_ + bc)*H_ + u];
            float c1 = sigm(gf)*(gh*c_reg[q]) + sigm(gi)*tanhf(gg);
            float h1 = sigm(go)*tanhf(c1);
            float gtv = sigm(tps[t]*wtr[q] + htr[q]);
            c_reg[q] = gtv*c1;
            stcg(&g_hbuf[p^1][bc][u], gtv*h1);
        }
        gridbar(grp, sense);
    }

    for (int i = tid; i < 512; i += 256)
        h1s[i] = ldcg(&g_hbuf[0][bc][i]);
    __syncthreads();
    {
        int wid = tid >> 5, lane = tid & 31;
        for (int z = wid; z < 10; z += 8) {
            float s = 0.f;
            const float* wv = g_W1T + z*H_;
            #pragma unroll 4
            for (int k = lane; k < H_; k += 32) s = fmaf(h1s[k], __ldg(&wv[k]), s);
            #pragma unroll
            for (int off = 16; off; off >>= 1) s += __shfl_xor_sync(0xffffffffu, s, off);
            if (lane == 0) zs[z] = sigm(s + b1[z]);
        }
        __syncthreads();
        if (tid == 0) {
            float z0 = b2[0], z1 = b2[1];
            #pragma unroll
            for (int j = 0; j < 10; j++) {
                z0 = fmaf(zs[j], W2[j*2 + 0], z0);
                z1 = fmaf(zs[j], W2[j*2 + 1], z1);
            }
            z0 = sigm(z0); z1 = sigm(z1);
            float m = fmaxf(z0, z1);
            float e0 = expf(z0 - m), e1 = expf(z1 - m);
            float inv = 1.f/(e0 + e1);
            out[((size_t)127*B_ + bc)*2 + 0] = e0*inv;
            out[((size_t)127*B_ + bc)*2 + 1] = e1*inv;
        }
    }
}

// ---------------------------------------------------------------------------
extern "C" void kernel_launch(void* const* d_in, const int* in_sizes, int n_in,
                              void* d_out, int out_size)
{
    const float* x     = (const float*)d_in[0];
    const float* dt    = (const float*)d_in[1];
    const float* mask  = (const float*)d_in[2];
    const float* tp    = (const float*)d_in[3];
    const float* xmean = (const float*)d_in[4];
    const float* h0    = (const float*)d_in[5];
    const float* c0    = (const float*)d_in[6];
    const float* wgx   = (const float*)d_in[7];
    const float* hgx   = (const float*)d_in[8];
    const float* wgh   = (const float*)d_in[9];
    const float* hgh   = (const float*)d_in[10];
    const float* wt    = (const float*)d_in[11];
    const float* ht    = (const float*)d_in[12];
    const float* Wih   = (const float*)d_in[13];
    const float* Whh   = (const float*)d_in[14];
    const float* bih   = (const float*)d_in[15];
    const float* bhh   = (const float*)d_in[16];
    const float* W1    = (const float*)d_in[17];
    const float* b1    = (const float*)d_in[18];
    const float* W2    = (const float*)d_in[19];
    const float* b2    = (const float*)d_in[20];
    float* out = (float*)d_out;

    const int LOOP_SMEM = (192*LDK + 512 + 16 + 128) * 4;
    static bool attr_done = false;
    if (!attr_done) {
        cudaFuncSetAttribute(k_g12_h, cudaFuncAttributeMaxDynamicSharedMemorySize, HM_SMEM);
        cudaFuncSetAttribute(k_g3_h,  cudaFuncAttributeMaxDynamicSharedMemorySize, HM_SMEM);
        cudaFuncSetAttribute(k_loop,  cudaFuncAttributeMaxDynamicSharedMemorySize, LOOP_SMEM);
        attr_done = true;
    }

    k_init<<<B_, H_>>>(h0);
    k_tr<<<778, 256>>>(wgx, wgh, W1);
    k_g12_h<<<dim3(BT_/128, 6),  256, HM_SMEM>>>(dt, hgx, hgh, x, mask, xmean, out);
    k_g3_h<<<dim3(BT_/128, 16), 256, HM_SMEM>>>(out + XHAT_OFF, Wih, bih, bhh);
    k_loop<<<256, 256, LOOP_SMEM>>>(Whh, c0, tp, wt, ht, b1, W2, b2, out);
}